// round 1
// baseline (speedup 1.0000x reference)
#include <cuda_runtime.h>
#include <cuda_bf16.h>

// Problem constants
#define BATCH 2
#define SEQ   2048
#define DMODEL 2048
#define NHEAD 16
#define HDIM  128
#define MROWS (BATCH * SEQ)          // 4096
#define SCALE 0.08838834764831845f   // 1/sqrt(128)

// -------------------- scratch (static device globals; no allocs) ------------
__device__ float g_Q[(size_t)MROWS * DMODEL];            // 33.5 MB  [b*S+s][h*128+d]
__device__ float g_K[(size_t)MROWS * HDIM];              // 2 MB     [b*S+s][d]
__device__ float g_V[(size_t)MROWS * HDIM];              // 2 MB
__device__ float g_S[(size_t)BATCH * NHEAD * SEQ * SEQ]; // 512 MB   [p][s][t]
__device__ float g_H[(size_t)MROWS * DMODEL];            // 33.5 MB  [b*S+s][h*128+d]

// -------------------- generic register-blocked SGEMM tile -------------------
// C[row0..row0+BM, col0..col0+BN] = alpha * A @ op(B)
// A: row-major [M x K], lda. B: row-major; if TRANSB, B is [N x K] and we use B^T.
template<int BM, int BN, int BK, int TM, int TN, bool TRANSB>
__device__ __forceinline__ void sgemm_block(
    const float* __restrict__ A, int lda,
    const float* __restrict__ B, int ldb,
    float* __restrict__ C, int ldc,
    int K, int row0, int col0, float alpha)
{
    constexpr int THREADS = (BM / TM) * (BN / TN);
    __shared__ float As[BK][BM];
    __shared__ float Bs[BK][BN];

    const int tid = threadIdx.x;
    const int tx = tid % (BN / TN);
    const int ty = tid / (BN / TN);

    float acc[TM][TN] = {};
    float ra[TM], rb[TN];

    for (int k0 = 0; k0 < K; k0 += BK) {
        // A tile: BM x BK -> As transposed [BK][BM]
        #pragma unroll
        for (int idx = tid * 4; idx < BM * BK; idx += THREADS * 4) {
            int r = idx / BK, c = idx % BK;
            float4 v = *(const float4*)(A + (size_t)(row0 + r) * lda + k0 + c);
            As[c + 0][r] = v.x; As[c + 1][r] = v.y;
            As[c + 2][r] = v.z; As[c + 3][r] = v.w;
        }
        if (!TRANSB) {
            // B tile: BK x BN -> Bs [BK][BN]
            #pragma unroll
            for (int idx = tid * 4; idx < BK * BN; idx += THREADS * 4) {
                int r = idx / BN, c = idx % BN;
                float4 v = *(const float4*)(B + (size_t)(k0 + r) * ldb + col0 + c);
                *(float4*)&Bs[r][c] = v;
            }
        } else {
            // B is [N x K]; Bs[kk][j] = B[col0+j][k0+kk]
            #pragma unroll
            for (int idx = tid * 4; idx < BN * BK; idx += THREADS * 4) {
                int r = idx / BK, c = idx % BK;   // r = j, c = k
                float4 v = *(const float4*)(B + (size_t)(col0 + r) * ldb + k0 + c);
                Bs[c + 0][r] = v.x; Bs[c + 1][r] = v.y;
                Bs[c + 2][r] = v.z; Bs[c + 3][r] = v.w;
            }
        }
        __syncthreads();

        #pragma unroll
        for (int kk = 0; kk < BK; kk++) {
            #pragma unroll
            for (int i = 0; i < TM; i++) ra[i] = As[kk][ty * TM + i];
            #pragma unroll
            for (int j = 0; j < TN; j++) rb[j] = Bs[kk][tx * TN + j];
            #pragma unroll
            for (int i = 0; i < TM; i++)
                #pragma unroll
                for (int j = 0; j < TN; j++)
                    acc[i][j] += ra[i] * rb[j];
        }
        __syncthreads();
    }

    #pragma unroll
    for (int i = 0; i < TM; i++) {
        #pragma unroll
        for (int j = 0; j < TN; j += 4) {
            float4 v;
            v.x = acc[i][j + 0] * alpha;
            v.y = acc[i][j + 1] * alpha;
            v.z = acc[i][j + 2] * alpha;
            v.w = acc[i][j + 3] * alpha;
            *(float4*)(C + (size_t)(row0 + ty * TM + i) * ldc + col0 + tx * TN + j) = v;
        }
    }
}

// -------------------- kernels ----------------------------------------------

// Q projection: g_Q = X @ Wq   (4096 x 2048 x 2048). grid (N/128, M/128)
__global__ __launch_bounds__(256) void gemm_qproj(const float* __restrict__ X,
                                                  const float* __restrict__ Wq) {
    sgemm_block<128, 128, 8, 8, 8, false>(X, DMODEL, Wq, DMODEL, g_Q, DMODEL,
                                          DMODEL, blockIdx.y * 128, blockIdx.x * 128, 1.0f);
}

// K/V projection (skinny): grid (1, M/32, 2), z=0 -> K, z=1 -> V
__global__ __launch_bounds__(256) void gemm_kv(const float* __restrict__ X,
                                               const float* __restrict__ Wk,
                                               const float* __restrict__ Wv) {
    const float* B = blockIdx.z ? Wv : Wk;
    float* C = blockIdx.z ? g_V : g_K;
    sgemm_block<32, 128, 8, 4, 4, false>(X, DMODEL, B, HDIM, C, HDIM,
                                         DMODEL, blockIdx.y * 32, 0, 1.0f);
}

// Scores: S[p] = SCALE * Q_head[p] @ K_b^T   per batch-head p. grid (16,16,32)
__global__ __launch_bounds__(256) void gemm_scores() {
    int p = blockIdx.z, b = p >> 4, h = p & 15;
    const float* A = g_Q + (size_t)b * SEQ * DMODEL + (size_t)h * HDIM;
    const float* B = g_K + (size_t)b * SEQ * HDIM;
    float* C = g_S + (size_t)p * SEQ * SEQ;
    sgemm_block<128, 128, 8, 8, 8, true>(A, DMODEL, B, HDIM, C, SEQ,
                                         HDIM, blockIdx.y * 128, blockIdx.x * 128, SCALE);
}

// Row softmax over g_S, 1 block (256 thr) per row of 2048
__global__ __launch_bounds__(256) void softmax_kernel() {
    const int t = threadIdx.x;
    float* row = g_S + (size_t)blockIdx.x * SEQ;
    float4 a = reinterpret_cast<float4*>(row)[t];
    float4 c = reinterpret_cast<float4*>(row)[t + 256];

    float m = fmaxf(fmaxf(fmaxf(a.x, a.y), fmaxf(a.z, a.w)),
                    fmaxf(fmaxf(c.x, c.y), fmaxf(c.z, c.w)));
    __shared__ float sred[8];
    #pragma unroll
    for (int o = 16; o > 0; o >>= 1) m = fmaxf(m, __shfl_xor_sync(0xffffffffu, m, o));
    if ((t & 31) == 0) sred[t >> 5] = m;
    __syncthreads();
    m = sred[0];
    #pragma unroll
    for (int i = 1; i < 8; i++) m = fmaxf(m, sred[i]);
    __syncthreads();

    a.x = __expf(a.x - m); a.y = __expf(a.y - m);
    a.z = __expf(a.z - m); a.w = __expf(a.w - m);
    c.x = __expf(c.x - m); c.y = __expf(c.y - m);
    c.z = __expf(c.z - m); c.w = __expf(c.w - m);

    float s = a.x + a.y + a.z + a.w + c.x + c.y + c.z + c.w;
    #pragma unroll
    for (int o = 16; o > 0; o >>= 1) s += __shfl_xor_sync(0xffffffffu, s, o);
    if ((t & 31) == 0) sred[t >> 5] = s;
    __syncthreads();
    s = sred[0];
    #pragma unroll
    for (int i = 1; i < 8; i++) s += sred[i];

    float inv = 1.0f / s;
    a.x *= inv; a.y *= inv; a.z *= inv; a.w *= inv;
    c.x *= inv; c.y *= inv; c.z *= inv; c.w *= inv;
    reinterpret_cast<float4*>(row)[t] = a;
    reinterpret_cast<float4*>(row)[t + 256] = c;
}

// head_out: H[b,s,h*128..] = attn[p] @ V_b   per batch-head p. grid (1,16,32)
__global__ __launch_bounds__(256) void gemm_av() {
    int p = blockIdx.z, b = p >> 4, h = p & 15;
    const float* A = g_S + (size_t)p * SEQ * SEQ;
    const float* B = g_V + (size_t)b * SEQ * HDIM;
    float* C = g_H + (size_t)b * SEQ * DMODEL + (size_t)h * HDIM;
    sgemm_block<128, 128, 8, 8, 8, false>(A, SEQ, B, HDIM, C, DMODEL,
                                          SEQ, blockIdx.y * 128, 0, 1.0f);
}

// Output projection: out = H @ Wo. grid (16, 32)
__global__ __launch_bounds__(256) void gemm_outproj(const float* __restrict__ Wo,
                                                    float* __restrict__ out) {
    sgemm_block<128, 128, 8, 8, 8, false>(g_H, DMODEL, Wo, DMODEL, out, DMODEL,
                                          DMODEL, blockIdx.y * 128, blockIdx.x * 128, 1.0f);
}

// -------------------- launch -----------------------------------------------
extern "C" void kernel_launch(void* const* d_in, const int* in_sizes, int n_in,
                              void* d_out, int out_size) {
    const float* X  = (const float*)d_in[0];
    const float* Wq = (const float*)d_in[1];
    const float* Wk = (const float*)d_in[2];
    const float* Wv = (const float*)d_in[3];
    const float* Wo = (const float*)d_in[4];
    float* out = (float*)d_out;

    gemm_qproj  <<<dim3(DMODEL / 128, MROWS / 128), 256>>>(X, Wq);
    gemm_kv     <<<dim3(1, MROWS / 32, 2),          256>>>(X, Wk, Wv);
    gemm_scores <<<dim3(SEQ / 128, SEQ / 128, BATCH * NHEAD), 256>>>();
    softmax_kernel<<<BATCH * NHEAD * SEQ, 256>>>();
    gemm_av     <<<dim3(1, SEQ / 128, BATCH * NHEAD), 256>>>();
    gemm_outproj<<<dim3(DMODEL / 128, MROWS / 128), 256>>>(Wo, out);
}

// round 3
// speedup vs baseline: 2.9522x; 2.9522x over previous
#include <cuda_runtime.h>
#include <cuda_bf16.h>
#include <cstdint>

#define BATCH 2
#define SEQ   2048
#define DMODEL 2048
#define NHEAD 16
#define HDIM  128
#define MROWS (BATCH * SEQ)
#define SCALE 0.08838834764831845f

typedef __nv_bfloat16 bf16;

// ------------------------- scratch (device globals) -------------------------
__device__ __align__(128) bf16 g_Xhi[(size_t)MROWS * DMODEL];
__device__ __align__(128) bf16 g_Xlo[(size_t)MROWS * DMODEL];
__device__ __align__(128) bf16 g_WqThi[(size_t)DMODEL * DMODEL];
__device__ __align__(128) bf16 g_WqTlo[(size_t)DMODEL * DMODEL];
__device__ __align__(128) bf16 g_WoThi[(size_t)DMODEL * DMODEL];
__device__ __align__(128) bf16 g_WoTlo[(size_t)DMODEL * DMODEL];
__device__ __align__(128) bf16 g_WkThi[(size_t)HDIM * DMODEL];
__device__ __align__(128) bf16 g_WkTlo[(size_t)HDIM * DMODEL];
__device__ __align__(128) bf16 g_WvThi[(size_t)HDIM * DMODEL];
__device__ __align__(128) bf16 g_WvTlo[(size_t)HDIM * DMODEL];
__device__ __align__(128) bf16 g_Qhi[(size_t)MROWS * DMODEL];
__device__ __align__(128) bf16 g_Qlo[(size_t)MROWS * DMODEL];
__device__ __align__(128) bf16 g_Khi[(size_t)MROWS * HDIM];
__device__ __align__(128) bf16 g_Klo[(size_t)MROWS * HDIM];
__device__ __align__(128) float g_Vf[(size_t)MROWS * HDIM];
__device__ __align__(128) bf16 g_VThi[(size_t)BATCH * HDIM * SEQ];
__device__ __align__(128) bf16 g_VTlo[(size_t)BATCH * HDIM * SEQ];
__device__ __align__(128) float g_S[(size_t)BATCH * NHEAD * SEQ * SEQ];   // 512 MB
__device__ __align__(128) bf16 g_Phi[(size_t)BATCH * NHEAD * SEQ * SEQ];  // 256 MB
__device__ __align__(128) bf16 g_Plo[(size_t)BATCH * NHEAD * SEQ * SEQ];  // 256 MB
__device__ __align__(128) bf16 g_Hhi[(size_t)MROWS * DMODEL];
__device__ __align__(128) bf16 g_Hlo[(size_t)MROWS * DMODEL];

// ------------------------- PTX helpers --------------------------------------
__device__ __forceinline__ uint32_t cvta_s(const void* p) {
    uint32_t a;
    asm("{ .reg .u64 t; cvta.to.shared.u64 t, %1; cvt.u32.u64 %0, t; }"
        : "=r"(a) : "l"(p));
    return a;
}
__device__ __forceinline__ void cp16(uint32_t s, const void* g) {
    asm volatile("cp.async.cg.shared.global [%0], [%1], 16;" :: "r"(s), "l"(g));
}
__device__ __forceinline__ void ldsm4(uint32_t* r, uint32_t addr) {
    asm volatile("ldmatrix.sync.aligned.m8n8.x4.shared.b16 {%0,%1,%2,%3}, [%4];"
                 : "=r"(r[0]), "=r"(r[1]), "=r"(r[2]), "=r"(r[3]) : "r"(addr));
}
__device__ __forceinline__ void mma16816(float* c, const uint32_t* a, const uint32_t* b) {
    asm volatile(
        "mma.sync.aligned.m16n8k16.row.col.f32.bf16.bf16.f32 "
        "{%0,%1,%2,%3}, {%4,%5,%6,%7}, {%8,%9}, {%0,%1,%2,%3};"
        : "+f"(c[0]), "+f"(c[1]), "+f"(c[2]), "+f"(c[3])
        : "r"(a[0]), "r"(a[1]), "r"(a[2]), "r"(a[3]), "r"(b[0]), "r"(b[1]));
}
__device__ __forceinline__ void split1(float x, bf16& h, bf16& l) {
    h = __float2bfloat16(x);
    l = __float2bfloat16(x - __bfloat162float(h));
}

// ------------------------- split-bf16 warp-MMA GEMM --------------------------
// C[row0:+128, col0:+128] = alpha * A @ B^T.  A:[M,K] lda, B:[N,K] ldb, K-major,
// both as hi/lo bf16 pairs. mode 0: write fp32 Cf. mode 1: write split Chi/Clo.
// 256 threads. SMEM/stage: Ahi|Alo|Bhi|Blo, 16KB each (128 rows x 128B, SW128).
template<int STAGES>
__device__ __forceinline__ void gemm_tc(
    const bf16* __restrict__ Ahi, const bf16* __restrict__ Alo, int lda,
    const bf16* __restrict__ Bhi, const bf16* __restrict__ Blo, int ldb,
    int K, int row0, int col0, int mode, float alpha,
    float* __restrict__ Cf, bf16* __restrict__ Chi, bf16* __restrict__ Clo, int ldc)
{
    extern __shared__ char dsm[];
    const int tid = threadIdx.x, wid = tid >> 5, l = tid & 31;
    const int wm = (wid & 3) * 32;       // warp m-offset in CTA tile
    const int wn = (wid >> 2) * 64;      // warp n-offset
    const uint32_t sbase = cvta_s(dsm);
    const int n = K >> 6;

    float acc[2][8][4] = {};

    auto load_chunk = [&](int k) {
        uint32_t sb = sbase + (uint32_t)(k % STAGES) * 65536u;
        int k0 = k << 6;
        #pragma unroll
        for (int i = tid; i < 1024; i += 256) {   // A: 128 rows x 8 16B-chunks
            int r = i >> 3, c = i & 7;
            uint32_t off = (uint32_t)(r * 128) + ((uint32_t)(c ^ (r & 7)) << 4);
            size_t ge = (size_t)(row0 + r) * lda + k0 + c * 8;
            cp16(sb + off, Ahi + ge);
            cp16(sb + 16384u + off, Alo + ge);
        }
        #pragma unroll
        for (int i = tid; i < 1024; i += 256) {   // B: 128 rows
            int r = i >> 3, c = i & 7;
            uint32_t off = (uint32_t)(r * 128) + ((uint32_t)(c ^ (r & 7)) << 4);
            size_t ge = (size_t)(col0 + r) * ldb + k0 + c * 8;
            cp16(sb + 32768u + off, Bhi + ge);
            cp16(sb + 49152u + off, Blo + ge);
        }
        asm volatile("cp.async.commit_group;" ::: "memory");
    };

    for (int k = 0; k < STAGES - 1 && k < n; k++) load_chunk(k);

    // ldmatrix lane address components (constant across k)
    const int at = l >> 3;                           // A tile id 0..3
    const int arow = ((at & 1) << 3) + (l & 7);      // + mi*16 + wm
    const uint32_t acolx = (uint32_t)((at >> 1) << 4);
    const int brow = (((l >> 4) & 1) << 3) + (l & 7);
    const uint32_t bcolx = (uint32_t)(((l >> 3) & 1) << 4);

    for (int k = 0; k < n; k++) {
        asm volatile("cp.async.wait_group %0;" :: "n"(STAGES - 2) : "memory");
        __syncthreads();
        int kp = k + STAGES - 1;
        if (kp < n) load_chunk(kp);
        else asm volatile("cp.async.commit_group;" ::: "memory");

        uint32_t sA = sbase + (uint32_t)(k % STAGES) * 65536u;
        uint32_t sB = sA + 32768u;
        #pragma unroll
        for (int ks = 0; ks < 4; ks++) {
            const uint32_t koff = (uint32_t)(ks << 5);
            uint32_t ah[2][4], al_[2][4];
            #pragma unroll
            for (int mi = 0; mi < 2; mi++) {
                int r = wm + mi * 16 + arow;
                uint32_t c = (koff + acolx) ^ ((uint32_t)(r & 7) << 4);
                ldsm4(ah[mi], sA + (uint32_t)(r * 128) + c);
                ldsm4(al_[mi], sA + 16384u + (uint32_t)(r * 128) + c);
            }
            uint32_t bh[4][4], bl_[4][4];
            #pragma unroll
            for (int nj = 0; nj < 4; nj++) {
                int r = wn + nj * 16 + brow;
                uint32_t c = (koff + bcolx) ^ ((uint32_t)(r & 7) << 4);
                ldsm4(bh[nj], sB + (uint32_t)(r * 128) + c);
                ldsm4(bl_[nj], sB + 16384u + (uint32_t)(r * 128) + c);
            }
            #pragma unroll
            for (int mi = 0; mi < 2; mi++)
                #pragma unroll
                for (int ni = 0; ni < 8; ni++) {
                    float* c = acc[mi][ni];
                    const uint32_t* bf = &bh[ni >> 1][(ni & 1) * 2];
                    const uint32_t* blf = &bl_[ni >> 1][(ni & 1) * 2];
                    mma16816(c, ah[mi], bf);
                    mma16816(c, ah[mi], blf);
                    mma16816(c, al_[mi], bf);
                }
        }
    }

    // epilogue
    #pragma unroll
    for (int mi = 0; mi < 2; mi++) {
        #pragma unroll
        for (int ni = 0; ni < 8; ni++) {
            int r0r = row0 + wm + mi * 16 + (l >> 2);
            int col = col0 + wn + ni * 8 + (l & 3) * 2;
            float c0 = acc[mi][ni][0], c1 = acc[mi][ni][1];
            float c2 = acc[mi][ni][2], c3 = acc[mi][ni][3];
            if (mode == 0) {
                float2 v0 = make_float2(c0 * alpha, c1 * alpha);
                float2 v1 = make_float2(c2 * alpha, c3 * alpha);
                *(float2*)(Cf + (size_t)r0r * ldc + col) = v0;
                *(float2*)(Cf + (size_t)(r0r + 8) * ldc + col) = v1;
            } else {
                bf16 h0, l0, h1, l1, h2, l2, h3, l3;
                split1(c0, h0, l0); split1(c1, h1, l1);
                split1(c2, h2, l2); split1(c3, h3, l3);
                __nv_bfloat162 p;
                p.x = h0; p.y = h1;
                *(__nv_bfloat162*)(Chi + (size_t)r0r * ldc + col) = p;
                p.x = l0; p.y = l1;
                *(__nv_bfloat162*)(Clo + (size_t)r0r * ldc + col) = p;
                p.x = h2; p.y = h3;
                *(__nv_bfloat162*)(Chi + (size_t)(r0r + 8) * ldc + col) = p;
                p.x = l2; p.y = l3;
                *(__nv_bfloat162*)(Clo + (size_t)(r0r + 8) * ldc + col) = p;
            }
        }
    }
}

// ------------------------- conversion kernels -------------------------------
__global__ __launch_bounds__(256) void k_split_x(const float* __restrict__ src) {
    size_t i = ((size_t)blockIdx.x * blockDim.x + threadIdx.x) * 4;
    if (i >= (size_t)MROWS * DMODEL) return;
    float4 v = *(const float4*)(src + i);
    bf16 h0, l0, h1, l1, h2, l2, h3, l3;
    split1(v.x, h0, l0); split1(v.y, h1, l1);
    split1(v.z, h2, l2); split1(v.w, h3, l3);
    __nv_bfloat162 a, b;
    a.x = h0; a.y = h1; b.x = h2; b.y = h3;
    *(__nv_bfloat162*)(g_Xhi + i) = a;
    *(__nv_bfloat162*)(g_Xhi + i + 2) = b;
    a.x = l0; a.y = l1; b.x = l2; b.y = l3;
    *(__nv_bfloat162*)(g_Xlo + i) = a;
    *(__nv_bfloat162*)(g_Xlo + i + 2) = b;
}

__device__ __forceinline__ void tr_split_body(const float* __restrict__ src,
                                              bf16* __restrict__ dhi,
                                              bf16* __restrict__ dlo,
                                              int R, int C) {
    __shared__ float t[32][33];
    int r0 = blockIdx.y * 32, c0 = blockIdx.x * 32;
    int tx = threadIdx.x, ty = threadIdx.y;  // 32 x 8
    #pragma unroll
    for (int j = 0; j < 4; j++)
        t[ty + j * 8][tx] = src[(size_t)(r0 + ty + j * 8) * C + c0 + tx];
    __syncthreads();
    #pragma unroll
    for (int j = 0; j < 4; j++) {
        float v = t[tx][ty + j * 8];
        bf16 h, l;
        split1(v, h, l);
        size_t o = (size_t)(c0 + ty + j * 8) * R + r0 + tx;
        dhi[o] = h;
        dlo[o] = l;
    }
}

__global__ void k_tr_w(const float* __restrict__ src, int which, int R, int C) {
    bf16 *dh, *dl;
    if (which == 0)      { dh = g_WqThi; dl = g_WqTlo; }
    else if (which == 1) { dh = g_WkThi; dl = g_WkTlo; }
    else if (which == 2) { dh = g_WvThi; dl = g_WvTlo; }
    else                 { dh = g_WoThi; dl = g_WoTlo; }
    tr_split_body(src, dh, dl, R, C);
}

__global__ void k_tr_v() {
    int b = blockIdx.z;
    tr_split_body(g_Vf + (size_t)b * SEQ * HDIM,
                  g_VThi + (size_t)b * HDIM * SEQ,
                  g_VTlo + (size_t)b * HDIM * SEQ, SEQ, HDIM);
}

// ------------------------- softmax (fp32 in, split-bf16 out) ----------------
__global__ __launch_bounds__(256) void k_softmax() {
    const int t = threadIdx.x;
    const size_t row = blockIdx.x;
    float* rs = g_S + row * SEQ;
    float4 a = ((float4*)rs)[t];
    float4 c = ((float4*)rs)[t + 256];

    float m = fmaxf(fmaxf(fmaxf(a.x, a.y), fmaxf(a.z, a.w)),
                    fmaxf(fmaxf(c.x, c.y), fmaxf(c.z, c.w)));
    __shared__ float sred[8];
    #pragma unroll
    for (int o = 16; o > 0; o >>= 1) m = fmaxf(m, __shfl_xor_sync(0xffffffffu, m, o));
    if ((t & 31) == 0) sred[t >> 5] = m;
    __syncthreads();
    m = sred[0];
    #pragma unroll
    for (int i = 1; i < 8; i++) m = fmaxf(m, sred[i]);
    __syncthreads();

    a.x = __expf(a.x - m); a.y = __expf(a.y - m);
    a.z = __expf(a.z - m); a.w = __expf(a.w - m);
    c.x = __expf(c.x - m); c.y = __expf(c.y - m);
    c.z = __expf(c.z - m); c.w = __expf(c.w - m);

    float s = a.x + a.y + a.z + a.w + c.x + c.y + c.z + c.w;
    #pragma unroll
    for (int o = 16; o > 0; o >>= 1) s += __shfl_xor_sync(0xffffffffu, s, o);
    if ((t & 31) == 0) sred[t >> 5] = s;
    __syncthreads();
    s = sred[0];
    #pragma unroll
    for (int i = 1; i < 8; i++) s += sred[i];

    float inv = 1.0f / s;
    bf16* ph = g_Phi + row * SEQ;
    bf16* pl = g_Plo + row * SEQ;
    float va[8] = {a.x * inv, a.y * inv, a.z * inv, a.w * inv,
                   c.x * inv, c.y * inv, c.z * inv, c.w * inv};
    #pragma unroll
    for (int g = 0; g < 2; g++) {
        int base = g ? (1024 + 4 * t) : (4 * t);
        #pragma unroll
        for (int u = 0; u < 2; u++) {
            bf16 h0, l0, h1, l1;
            split1(va[g * 4 + u * 2 + 0], h0, l0);
            split1(va[g * 4 + u * 2 + 1], h1, l1);
            __nv_bfloat162 hh; hh.x = h0; hh.y = h1;
            __nv_bfloat162 ll; ll.x = l0; ll.y = l1;
            *(__nv_bfloat162*)(ph + base + u * 2) = hh;
            *(__nv_bfloat162*)(pl + base + u * 2) = ll;
        }
    }
}

// ------------------------- GEMM wrapper kernels -----------------------------
__global__ __launch_bounds__(256) void k_qproj() {
    gemm_tc<3>(g_Xhi, g_Xlo, DMODEL, g_WqThi, g_WqTlo, DMODEL,
               DMODEL, blockIdx.y * 128, blockIdx.x * 128,
               1, 1.0f, nullptr, g_Qhi, g_Qlo, DMODEL);
}

__global__ __launch_bounds__(256) void k_kv() {
    const bf16* bh = blockIdx.z ? g_WvThi : g_WkThi;
    const bf16* bl = blockIdx.z ? g_WvTlo : g_WkTlo;
    int mode = blockIdx.z ? 0 : 1;   // K -> split, V -> fp32 (then transposed)
    gemm_tc<3>(g_Xhi, g_Xlo, DMODEL, bh, bl, DMODEL,
               DMODEL, blockIdx.y * 128, 0,
               mode, 1.0f, g_Vf, g_Khi, g_Klo, HDIM);
}

__global__ __launch_bounds__(256) void k_scores() {
    int p = blockIdx.z, b = p >> 4, h = p & 15;
    const bf16* ah = g_Qhi + (size_t)b * SEQ * DMODEL + (size_t)h * HDIM;
    const bf16* al = g_Qlo + (size_t)b * SEQ * DMODEL + (size_t)h * HDIM;
    const bf16* bh = g_Khi + (size_t)b * SEQ * HDIM;
    const bf16* bl = g_Klo + (size_t)b * SEQ * HDIM;
    float* cf = g_S + (size_t)p * SEQ * SEQ;
    gemm_tc<3>(ah, al, DMODEL, bh, bl, HDIM,
               HDIM, blockIdx.y * 128, blockIdx.x * 128,
               0, SCALE, cf, nullptr, nullptr, SEQ);
}

__global__ __launch_bounds__(256) void k_av() {
    int p = blockIdx.z, b = p >> 4, h = p & 15;
    const bf16* ah = g_Phi + (size_t)p * SEQ * SEQ;
    const bf16* al = g_Plo + (size_t)p * SEQ * SEQ;
    const bf16* bh = g_VThi + (size_t)b * HDIM * SEQ;
    const bf16* bl = g_VTlo + (size_t)b * HDIM * SEQ;
    bf16* ch = g_Hhi + (size_t)b * SEQ * DMODEL + (size_t)h * HDIM;
    bf16* cl = g_Hlo + (size_t)b * SEQ * DMODEL + (size_t)h * HDIM;
    gemm_tc<3>(ah, al, SEQ, bh, bl, SEQ,
               SEQ, blockIdx.y * 128, 0,
               1, 1.0f, nullptr, ch, cl, DMODEL);
}

__global__ __launch_bounds__(256) void k_outproj(float* __restrict__ out) {
    gemm_tc<3>(g_Hhi, g_Hlo, DMODEL, g_WoThi, g_WoTlo, DMODEL,
               DMODEL, blockIdx.y * 128, blockIdx.x * 128,
               0, 1.0f, out, nullptr, nullptr, DMODEL);
}

// ------------------------- launch -------------------------------------------
#define SMEM_GEMM (3 * 65536)

extern "C" void kernel_launch(void* const* d_in, const int* in_sizes, int n_in,
                              void* d_out, int out_size) {
    const float* X  = (const float*)d_in[0];
    const float* Wq = (const float*)d_in[1];
    const float* Wk = (const float*)d_in[2];
    const float* Wv = (const float*)d_in[3];
    const float* Wo = (const float*)d_in[4];
    float* out = (float*)d_out;

    static int attr_done = 0;
    if (!attr_done) {
        attr_done = 1;
        cudaFuncSetAttribute(k_qproj,   cudaFuncAttributeMaxDynamicSharedMemorySize, SMEM_GEMM);
        cudaFuncSetAttribute(k_kv,      cudaFuncAttributeMaxDynamicSharedMemorySize, SMEM_GEMM);
        cudaFuncSetAttribute(k_scores,  cudaFuncAttributeMaxDynamicSharedMemorySize, SMEM_GEMM);
        cudaFuncSetAttribute(k_av,      cudaFuncAttributeMaxDynamicSharedMemorySize, SMEM_GEMM);
        cudaFuncSetAttribute(k_outproj, cudaFuncAttributeMaxDynamicSharedMemorySize, SMEM_GEMM);
    }

    dim3 tb(32, 8);
    k_split_x<<<(MROWS * DMODEL / 4 + 255) / 256, 256>>>(X);
    k_tr_w<<<dim3(64, 64), tb>>>(Wq, 0, DMODEL, DMODEL);
    k_tr_w<<<dim3(4, 64),  tb>>>(Wk, 1, DMODEL, HDIM);
    k_tr_w<<<dim3(4, 64),  tb>>>(Wv, 2, DMODEL, HDIM);
    k_tr_w<<<dim3(64, 64), tb>>>(Wo, 3, DMODEL, DMODEL);

    k_qproj<<<dim3(DMODEL / 128, MROWS / 128), 256, SMEM_GEMM>>>();
    k_kv<<<dim3(1, MROWS / 128, 2), 256, SMEM_GEMM>>>();
    k_tr_v<<<dim3(HDIM / 32, SEQ / 32, BATCH), tb>>>();

    k_scores<<<dim3(SEQ / 128, SEQ / 128, BATCH * NHEAD), 256, SMEM_GEMM>>>();
    k_softmax<<<BATCH * NHEAD * SEQ, 256>>>();
    k_av<<<dim3(1, SEQ / 128, BATCH * NHEAD), 256, SMEM_GEMM>>>();
    k_outproj<<<dim3(DMODEL / 128, MROWS / 128), 256, SMEM_GEMM>>>(out);
}

// round 4
// speedup vs baseline: 3.5017x; 1.1861x over previous
#include <cuda_runtime.h>
#include <cuda_bf16.h>
#include <cstdint>

#define BATCH 2
#define SEQ   2048
#define DMODEL 2048
#define NHEAD 16
#define HDIM  128
#define MROWS (BATCH * SEQ)
#define SCALE 0.08838834764831845f

typedef __nv_bfloat16 bf16;

// ------------------------- scratch (device globals) -------------------------
__device__ __align__(128) bf16 g_Xhi[(size_t)MROWS * DMODEL];
__device__ __align__(128) bf16 g_Xlo[(size_t)MROWS * DMODEL];
__device__ __align__(128) bf16 g_WqThi[(size_t)DMODEL * DMODEL];
__device__ __align__(128) bf16 g_WqTlo[(size_t)DMODEL * DMODEL];
__device__ __align__(128) bf16 g_WoThi[(size_t)DMODEL * DMODEL];
__device__ __align__(128) bf16 g_WoTlo[(size_t)DMODEL * DMODEL];
__device__ __align__(128) bf16 g_WkThi[(size_t)HDIM * DMODEL];
__device__ __align__(128) bf16 g_WkTlo[(size_t)HDIM * DMODEL];
__device__ __align__(128) bf16 g_WvThi[(size_t)HDIM * DMODEL];
__device__ __align__(128) bf16 g_WvTlo[(size_t)HDIM * DMODEL];
__device__ __align__(128) bf16 g_Qhi[(size_t)MROWS * DMODEL];
__device__ __align__(128) bf16 g_Qlo[(size_t)MROWS * DMODEL];
__device__ __align__(128) bf16 g_Khi[(size_t)MROWS * HDIM];
__device__ __align__(128) bf16 g_Klo[(size_t)MROWS * HDIM];
__device__ __align__(128) float g_Vf[(size_t)MROWS * HDIM];
__device__ __align__(128) bf16 g_VThi[(size_t)BATCH * HDIM * SEQ];
__device__ __align__(128) bf16 g_VTlo[(size_t)BATCH * HDIM * SEQ];
__device__ __align__(128) bf16 g_Hhi[(size_t)MROWS * DMODEL];
__device__ __align__(128) bf16 g_Hlo[(size_t)MROWS * DMODEL];

// ------------------------- PTX helpers --------------------------------------
__device__ __forceinline__ uint32_t cvta_s(const void* p) {
    uint32_t a;
    asm("{ .reg .u64 t; cvta.to.shared.u64 t, %1; cvt.u32.u64 %0, t; }"
        : "=r"(a) : "l"(p));
    return a;
}
__device__ __forceinline__ void cp16(uint32_t s, const void* g) {
    asm volatile("cp.async.cg.shared.global [%0], [%1], 16;" :: "r"(s), "l"(g));
}
__device__ __forceinline__ void ldsm4(uint32_t* r, uint32_t addr) {
    asm volatile("ldmatrix.sync.aligned.m8n8.x4.shared.b16 {%0,%1,%2,%3}, [%4];"
                 : "=r"(r[0]), "=r"(r[1]), "=r"(r[2]), "=r"(r[3]) : "r"(addr));
}
__device__ __forceinline__ void mma16816(float* c, const uint32_t* a, const uint32_t* b) {
    asm volatile(
        "mma.sync.aligned.m16n8k16.row.col.f32.bf16.bf16.f32 "
        "{%0,%1,%2,%3}, {%4,%5,%6,%7}, {%8,%9}, {%0,%1,%2,%3};"
        : "+f"(c[0]), "+f"(c[1]), "+f"(c[2]), "+f"(c[3])
        : "r"(a[0]), "r"(a[1]), "r"(a[2]), "r"(a[3]), "r"(b[0]), "r"(b[1]));
}
__device__ __forceinline__ void split1(float x, bf16& h, bf16& l) {
    h = __float2bfloat16(x);
    l = __float2bfloat16(x - __bfloat162float(h));
}
__device__ __forceinline__ uint32_t packh(bf16 a, bf16 b) {
    __nv_bfloat162 t; t.x = a; t.y = b;
    return *(uint32_t*)&t;
}

// ------------------------- split-bf16 warp-MMA GEMM --------------------------
// (same core as round 3; used for the 3 projection GEMMs)
template<int STAGES>
__device__ __forceinline__ void gemm_tc(
    const bf16* __restrict__ Ahi, const bf16* __restrict__ Alo, int lda,
    const bf16* __restrict__ Bhi, const bf16* __restrict__ Blo, int ldb,
    int K, int row0, int col0, int mode, float alpha,
    float* __restrict__ Cf, bf16* __restrict__ Chi, bf16* __restrict__ Clo, int ldc)
{
    extern __shared__ char dsm[];
    const int tid = threadIdx.x, wid = tid >> 5, l = tid & 31;
    const int wm = (wid & 3) * 32;
    const int wn = (wid >> 2) * 64;
    const uint32_t sbase = cvta_s(dsm);
    const int n = K >> 6;

    float acc[2][8][4] = {};

    auto load_chunk = [&](int k) {
        uint32_t sb = sbase + (uint32_t)(k % STAGES) * 65536u;
        int k0 = k << 6;
        #pragma unroll
        for (int i = tid; i < 1024; i += 256) {
            int r = i >> 3, c = i & 7;
            uint32_t off = (uint32_t)(r * 128) + ((uint32_t)(c ^ (r & 7)) << 4);
            size_t ge = (size_t)(row0 + r) * lda + k0 + c * 8;
            cp16(sb + off, Ahi + ge);
            cp16(sb + 16384u + off, Alo + ge);
        }
        #pragma unroll
        for (int i = tid; i < 1024; i += 256) {
            int r = i >> 3, c = i & 7;
            uint32_t off = (uint32_t)(r * 128) + ((uint32_t)(c ^ (r & 7)) << 4);
            size_t ge = (size_t)(col0 + r) * ldb + k0 + c * 8;
            cp16(sb + 32768u + off, Bhi + ge);
            cp16(sb + 49152u + off, Blo + ge);
        }
        asm volatile("cp.async.commit_group;" ::: "memory");
    };

    for (int k = 0; k < STAGES - 1 && k < n; k++) load_chunk(k);

    const int at = l >> 3;
    const int arow = ((at & 1) << 3) + (l & 7);
    const uint32_t acolx = (uint32_t)((at >> 1) << 4);
    const int brow = (((l >> 4) & 1) << 3) + (l & 7);
    const uint32_t bcolx = (uint32_t)(((l >> 3) & 1) << 4);

    for (int k = 0; k < n; k++) {
        asm volatile("cp.async.wait_group %0;" :: "n"(STAGES - 2) : "memory");
        __syncthreads();
        int kp = k + STAGES - 1;
        if (kp < n) load_chunk(kp);
        else asm volatile("cp.async.commit_group;" ::: "memory");

        uint32_t sA = sbase + (uint32_t)(k % STAGES) * 65536u;
        uint32_t sB = sA + 32768u;
        #pragma unroll
        for (int ks = 0; ks < 4; ks++) {
            const uint32_t koff = (uint32_t)(ks << 5);
            uint32_t ah[2][4], al_[2][4];
            #pragma unroll
            for (int mi = 0; mi < 2; mi++) {
                int r = wm + mi * 16 + arow;
                uint32_t c = (koff + acolx) ^ ((uint32_t)(r & 7) << 4);
                ldsm4(ah[mi], sA + (uint32_t)(r * 128) + c);
                ldsm4(al_[mi], sA + 16384u + (uint32_t)(r * 128) + c);
            }
            uint32_t bh[4][4], bl_[4][4];
            #pragma unroll
            for (int nj = 0; nj < 4; nj++) {
                int r = wn + nj * 16 + brow;
                uint32_t c = (koff + bcolx) ^ ((uint32_t)(r & 7) << 4);
                ldsm4(bh[nj], sB + (uint32_t)(r * 128) + c);
                ldsm4(bl_[nj], sB + 16384u + (uint32_t)(r * 128) + c);
            }
            #pragma unroll
            for (int mi = 0; mi < 2; mi++)
                #pragma unroll
                for (int ni = 0; ni < 8; ni++) {
                    float* c = acc[mi][ni];
                    const uint32_t* bf = &bh[ni >> 1][(ni & 1) * 2];
                    const uint32_t* blf = &bl_[ni >> 1][(ni & 1) * 2];
                    mma16816(c, ah[mi], bf);
                    mma16816(c, ah[mi], blf);
                    mma16816(c, al_[mi], bf);
                }
        }
    }

    #pragma unroll
    for (int mi = 0; mi < 2; mi++) {
        #pragma unroll
        for (int ni = 0; ni < 8; ni++) {
            int r0r = row0 + wm + mi * 16 + (l >> 2);
            int col = col0 + wn + ni * 8 + (l & 3) * 2;
            float c0 = acc[mi][ni][0], c1 = acc[mi][ni][1];
            float c2 = acc[mi][ni][2], c3 = acc[mi][ni][3];
            if (mode == 0) {
                *(float2*)(Cf + (size_t)r0r * ldc + col) = make_float2(c0 * alpha, c1 * alpha);
                *(float2*)(Cf + (size_t)(r0r + 8) * ldc + col) = make_float2(c2 * alpha, c3 * alpha);
            } else {
                bf16 h0, l0, h1, l1, h2, l2, h3, l3;
                split1(c0, h0, l0); split1(c1, h1, l1);
                split1(c2, h2, l2); split1(c3, h3, l3);
                *(uint32_t*)(Chi + (size_t)r0r * ldc + col) = packh(h0, h1);
                *(uint32_t*)(Clo + (size_t)r0r * ldc + col) = packh(l0, l1);
                *(uint32_t*)(Chi + (size_t)(r0r + 8) * ldc + col) = packh(h2, h3);
                *(uint32_t*)(Clo + (size_t)(r0r + 8) * ldc + col) = packh(l2, l3);
            }
        }
    }
}

// ------------------------- fused flash attention -----------------------------
// Grid (SEQ/128, BATCH*NHEAD). 256 thr, 8 warps x m16 rows. K/V chunks of 64.
// SMEM: Qhi 32K | Qlo 32K | 2 stages x (Khi 16K | Klo 16K | VThi 16K | VTlo 16K)
#define FSTAGE 65536u
#define SMEM_FLASH 196608

__global__ __launch_bounds__(256, 1) void k_flash() {
    extern __shared__ char dsm[];
    const int tid = threadIdx.x, wid = tid >> 5, l = tid & 31;
    const int p = blockIdx.y, b = p >> 4, h = p & 15;
    const int q0 = blockIdx.x * 128;
    const bf16* Qh = g_Qhi + (size_t)b * SEQ * DMODEL + (size_t)h * HDIM;
    const bf16* Ql = g_Qlo + (size_t)b * SEQ * DMODEL + (size_t)h * HDIM;
    const bf16* Kh = g_Khi + (size_t)b * SEQ * HDIM;
    const bf16* Kl = g_Klo + (size_t)b * SEQ * HDIM;
    const bf16* Vh = g_VThi + (size_t)b * HDIM * SEQ;
    const bf16* Vl = g_VTlo + (size_t)b * HDIM * SEQ;
    const uint32_t sb = cvta_s(dsm);
    const uint32_t sQh = sb, sQl = sb + 32768u, sSt = sb + 65536u;

    // Q tile (128 x 128, 256B rows) — part of cp.async group 0
    #pragma unroll
    for (int i = tid; i < 2048; i += 256) {
        int r = i >> 4, c = i & 15;
        uint32_t off = (uint32_t)(r * 256) + (((uint32_t)(c * 16)) ^ ((uint32_t)(r & 7) << 4));
        size_t ge = (size_t)(q0 + r) * DMODEL + c * 8;
        cp16(sQh + off, Qh + ge);
        cp16(sQl + off, Ql + ge);
    }
    auto loadkv = [&](int kc) {
        uint32_t s = sSt + (uint32_t)(kc & 1) * FSTAGE;
        int key0 = kc * 64;
        #pragma unroll
        for (int i = tid; i < 1024; i += 256) {   // K: 64 rows x 256B
            int r = i >> 4, c = i & 15;
            uint32_t off = (uint32_t)(r * 256) + (((uint32_t)(c * 16)) ^ ((uint32_t)(r & 7) << 4));
            size_t ge = (size_t)(key0 + r) * HDIM + c * 8;
            cp16(s + off, Kh + ge);
            cp16(s + 16384u + off, Kl + ge);
        }
        #pragma unroll
        for (int i = tid; i < 1024; i += 256) {   // V^T: 128 rows x 128B
            int r = i >> 3, c = i & 7;
            uint32_t off = (uint32_t)(r * 128) + (((uint32_t)(c * 16)) ^ ((uint32_t)(r & 7) << 4));
            size_t ge = (size_t)r * SEQ + key0 + c * 8;
            cp16(s + 32768u + off, Vh + ge);
            cp16(s + 49152u + off, Vl + ge);
        }
        asm volatile("cp.async.commit_group;" ::: "memory");
    };
    loadkv(0);

    const int at = l >> 3;
    const int arow = ((at & 1) << 3) + (l & 7);
    const uint32_t acolx = (uint32_t)((at >> 1) << 4);
    const int brow = (((l >> 4) & 1) << 3) + (l & 7);
    const uint32_t bcolx = (uint32_t)(((l >> 3) & 1) << 4);
    const int m0 = wid * 16;

    float oacc[16][4] = {};
    float mrow0 = -1e30f, mrow1 = -1e30f, lsum0 = 0.f, lsum1 = 0.f;

    for (int kc = 0; kc < SEQ / 64; kc++) {
        if (kc + 1 < SEQ / 64) {
            loadkv(kc + 1);
            asm volatile("cp.async.wait_group 1;" ::: "memory");
        } else {
            asm volatile("cp.async.wait_group 0;" ::: "memory");
        }
        __syncthreads();
        uint32_t s = sSt + (uint32_t)(kc & 1) * FSTAGE;
        uint32_t sKh = s, sKl = s + 16384u, sVh = s + 32768u, sVl = s + 49152u;

        // S = Q @ K^T  (m16 x n64, k=128)
        float sacc[8][4] = {};
        #pragma unroll
        for (int ks = 0; ks < 8; ks++) {
            const uint32_t koff = (uint32_t)(ks << 5);
            int r = m0 + arow;
            uint32_t ac = (koff + acolx) ^ ((uint32_t)(r & 7) << 4);
            uint32_t ah[4], al_[4];
            ldsm4(ah, sQh + (uint32_t)(r * 256) + ac);
            ldsm4(al_, sQl + (uint32_t)(r * 256) + ac);
            uint32_t kh[4][4], kl_[4][4];
            #pragma unroll
            for (int nj = 0; nj < 4; nj++) {
                int rr = nj * 16 + brow;
                uint32_t cc = (koff + bcolx) ^ ((uint32_t)(rr & 7) << 4);
                ldsm4(kh[nj], sKh + (uint32_t)(rr * 256) + cc);
                ldsm4(kl_[nj], sKl + (uint32_t)(rr * 256) + cc);
            }
            #pragma unroll
            for (int ni = 0; ni < 8; ni++) {
                float* c = sacc[ni];
                const uint32_t* bh_ = &kh[ni >> 1][(ni & 1) * 2];
                const uint32_t* bl2 = &kl_[ni >> 1][(ni & 1) * 2];
                mma16816(c, ah, bh_);
                mma16816(c, ah, bl2);
                mma16816(c, al_, bh_);
            }
        }

        // online softmax (rows l/4 and l/4+8; 4-lane quad owns a row)
        float mx0 = -1e30f, mx1 = -1e30f;
        #pragma unroll
        for (int ni = 0; ni < 8; ni++) {
            sacc[ni][0] *= SCALE; sacc[ni][1] *= SCALE;
            sacc[ni][2] *= SCALE; sacc[ni][3] *= SCALE;
            mx0 = fmaxf(mx0, fmaxf(sacc[ni][0], sacc[ni][1]));
            mx1 = fmaxf(mx1, fmaxf(sacc[ni][2], sacc[ni][3]));
        }
        mx0 = fmaxf(mx0, __shfl_xor_sync(0xffffffffu, mx0, 1));
        mx0 = fmaxf(mx0, __shfl_xor_sync(0xffffffffu, mx0, 2));
        mx1 = fmaxf(mx1, __shfl_xor_sync(0xffffffffu, mx1, 1));
        mx1 = fmaxf(mx1, __shfl_xor_sync(0xffffffffu, mx1, 2));
        float mn0 = fmaxf(mrow0, mx0), mn1 = fmaxf(mrow1, mx1);
        float a0 = __expf(mrow0 - mn0), a1 = __expf(mrow1 - mn1);
        mrow0 = mn0; mrow1 = mn1;
        float ps0 = 0.f, ps1 = 0.f;
        #pragma unroll
        for (int ni = 0; ni < 8; ni++) {
            sacc[ni][0] = __expf(sacc[ni][0] - mn0);
            sacc[ni][1] = __expf(sacc[ni][1] - mn0);
            sacc[ni][2] = __expf(sacc[ni][2] - mn1);
            sacc[ni][3] = __expf(sacc[ni][3] - mn1);
            ps0 += sacc[ni][0] + sacc[ni][1];
            ps1 += sacc[ni][2] + sacc[ni][3];
        }
        lsum0 = lsum0 * a0 + ps0;
        lsum1 = lsum1 * a1 + ps1;
        #pragma unroll
        for (int ni = 0; ni < 16; ni++) {
            oacc[ni][0] *= a0; oacc[ni][1] *= a0;
            oacc[ni][2] *= a1; oacc[ni][3] *= a1;
        }

        // O += P @ V  (A = P frags from registers, B = V^T tiles)
        #pragma unroll
        for (int j = 0; j < 4; j++) {
            uint32_t phi[4], plo[4];
            #pragma unroll
            for (int t2 = 0; t2 < 2; t2++) {
                float x0 = sacc[2 * j + t2][0], x1 = sacc[2 * j + t2][1];
                float x2 = sacc[2 * j + t2][2], x3 = sacc[2 * j + t2][3];
                bf16 h0, l0, h1, l1, h2, l2, h3, l3;
                split1(x0, h0, l0); split1(x1, h1, l1);
                split1(x2, h2, l2); split1(x3, h3, l3);
                phi[t2 * 2 + 0] = packh(h0, h1);
                phi[t2 * 2 + 1] = packh(h2, h3);
                plo[t2 * 2 + 0] = packh(l0, l1);
                plo[t2 * 2 + 1] = packh(l2, l3);
            }
            #pragma unroll
            for (int nj = 0; nj < 8; nj++) {
                int rr = nj * 16 + brow;
                uint32_t cc = ((uint32_t)(j << 5) + bcolx) ^ ((uint32_t)(rr & 7) << 4);
                uint32_t vh4[4], vl4[4];
                ldsm4(vh4, sVh + (uint32_t)(rr * 128) + cc);
                ldsm4(vl4, sVl + (uint32_t)(rr * 128) + cc);
                #pragma unroll
                for (int t2 = 0; t2 < 2; t2++) {
                    float* o = oacc[nj * 2 + t2];
                    mma16816(o, phi, &vh4[t2 * 2]);
                    mma16816(o, phi, &vl4[t2 * 2]);
                    mma16816(o, plo, &vh4[t2 * 2]);
                }
            }
        }
        __syncthreads();   // stage reuse hazard vs next loadkv
    }

    // epilogue: normalize, split, store H
    lsum0 += __shfl_xor_sync(0xffffffffu, lsum0, 1);
    lsum0 += __shfl_xor_sync(0xffffffffu, lsum0, 2);
    lsum1 += __shfl_xor_sync(0xffffffffu, lsum1, 1);
    lsum1 += __shfl_xor_sync(0xffffffffu, lsum1, 2);
    float inv0 = 1.0f / lsum0, inv1 = 1.0f / lsum1;
    bf16* Hh = g_Hhi + (size_t)b * SEQ * DMODEL + (size_t)h * HDIM;
    bf16* Hl = g_Hlo + (size_t)b * SEQ * DMODEL + (size_t)h * HDIM;
    const int r0r = q0 + m0 + (l >> 2);
    const int colb = (l & 3) * 2;
    #pragma unroll
    for (int nj = 0; nj < 16; nj++) {
        float x0 = oacc[nj][0] * inv0, x1 = oacc[nj][1] * inv0;
        float x2 = oacc[nj][2] * inv1, x3 = oacc[nj][3] * inv1;
        bf16 h0, l0, h1, l1, h2, l2, h3, l3;
        split1(x0, h0, l0); split1(x1, h1, l1);
        split1(x2, h2, l2); split1(x3, h3, l3);
        int col = nj * 8 + colb;
        *(uint32_t*)(Hh + (size_t)r0r * DMODEL + col) = packh(h0, h1);
        *(uint32_t*)(Hl + (size_t)r0r * DMODEL + col) = packh(l0, l1);
        *(uint32_t*)(Hh + (size_t)(r0r + 8) * DMODEL + col) = packh(h2, h3);
        *(uint32_t*)(Hl + (size_t)(r0r + 8) * DMODEL + col) = packh(l2, l3);
    }
}

// ------------------------- conversion kernels -------------------------------
__global__ __launch_bounds__(256) void k_split_x(const float* __restrict__ src) {
    size_t i = ((size_t)blockIdx.x * blockDim.x + threadIdx.x) * 4;
    if (i >= (size_t)MROWS * DMODEL) return;
    float4 v = *(const float4*)(src + i);
    bf16 h0, l0, h1, l1, h2, l2, h3, l3;
    split1(v.x, h0, l0); split1(v.y, h1, l1);
    split1(v.z, h2, l2); split1(v.w, h3, l3);
    *(uint32_t*)(g_Xhi + i) = packh(h0, h1);
    *(uint32_t*)(g_Xhi + i + 2) = packh(h2, h3);
    *(uint32_t*)(g_Xlo + i) = packh(l0, l1);
    *(uint32_t*)(g_Xlo + i + 2) = packh(l2, l3);
}

__device__ __forceinline__ void tr_split_body(const float* __restrict__ src,
                                              bf16* __restrict__ dhi,
                                              bf16* __restrict__ dlo,
                                              int R, int C) {
    __shared__ float t[32][33];
    int r0 = blockIdx.y * 32, c0 = blockIdx.x * 32;
    int tx = threadIdx.x, ty = threadIdx.y;  // 32 x 8
    #pragma unroll
    for (int j = 0; j < 4; j++)
        t[ty + j * 8][tx] = src[(size_t)(r0 + ty + j * 8) * C + c0 + tx];
    __syncthreads();
    #pragma unroll
    for (int j = 0; j < 4; j++) {
        float v = t[tx][ty + j * 8];
        bf16 h, l;
        split1(v, h, l);
        size_t o = (size_t)(c0 + ty + j * 8) * R + r0 + tx;
        dhi[o] = h;
        dlo[o] = l;
    }
}

__global__ void k_tr_w(const float* __restrict__ src, int which, int R, int C) {
    bf16 *dh, *dl;
    if (which == 0)      { dh = g_WqThi; dl = g_WqTlo; }
    else if (which == 1) { dh = g_WkThi; dl = g_WkTlo; }
    else if (which == 2) { dh = g_WvThi; dl = g_WvTlo; }
    else                 { dh = g_WoThi; dl = g_WoTlo; }
    tr_split_body(src, dh, dl, R, C);
}

__global__ void k_tr_v() {
    int b = blockIdx.z;
    tr_split_body(g_Vf + (size_t)b * SEQ * HDIM,
                  g_VThi + (size_t)b * HDIM * SEQ,
                  g_VTlo + (size_t)b * HDIM * SEQ, SEQ, HDIM);
}

// ------------------------- GEMM wrapper kernels -----------------------------
__global__ __launch_bounds__(256) void k_qproj() {
    gemm_tc<3>(g_Xhi, g_Xlo, DMODEL, g_WqThi, g_WqTlo, DMODEL,
               DMODEL, blockIdx.y * 128, blockIdx.x * 128,
               1, 1.0f, nullptr, g_Qhi, g_Qlo, DMODEL);
}

__global__ __launch_bounds__(256) void k_kv() {
    const bf16* bh = blockIdx.z ? g_WvThi : g_WkThi;
    const bf16* bl = blockIdx.z ? g_WvTlo : g_WkTlo;
    int mode = blockIdx.z ? 0 : 1;   // K -> split, V -> fp32 (then transposed)
    gemm_tc<3>(g_Xhi, g_Xlo, DMODEL, bh, bl, DMODEL,
               DMODEL, blockIdx.y * 128, 0,
               mode, 1.0f, g_Vf, g_Khi, g_Klo, HDIM);
}

__global__ __launch_bounds__(256) void k_outproj(float* __restrict__ out) {
    gemm_tc<3>(g_Hhi, g_Hlo, DMODEL, g_WoThi, g_WoTlo, DMODEL,
               DMODEL, blockIdx.y * 128, blockIdx.x * 128,
               0, 1.0f, out, nullptr, nullptr, DMODEL);
}

// ------------------------- launch -------------------------------------------
#define SMEM_GEMM (3 * 65536)

extern "C" void kernel_launch(void* const* d_in, const int* in_sizes, int n_in,
                              void* d_out, int out_size) {
    const float* X  = (const float*)d_in[0];
    const float* Wq = (const float*)d_in[1];
    const float* Wk = (const float*)d_in[2];
    const float* Wv = (const float*)d_in[3];
    const float* Wo = (const float*)d_in[4];
    float* out = (float*)d_out;

    static int attr_done = 0;
    if (!attr_done) {
        attr_done = 1;
        cudaFuncSetAttribute(k_qproj,   cudaFuncAttributeMaxDynamicSharedMemorySize, SMEM_GEMM);
        cudaFuncSetAttribute(k_kv,      cudaFuncAttributeMaxDynamicSharedMemorySize, SMEM_GEMM);
        cudaFuncSetAttribute(k_outproj, cudaFuncAttributeMaxDynamicSharedMemorySize, SMEM_GEMM);
        cudaFuncSetAttribute(k_flash,   cudaFuncAttributeMaxDynamicSharedMemorySize, SMEM_FLASH);
    }

    dim3 tb(32, 8);
    k_split_x<<<(MROWS * DMODEL / 4 + 255) / 256, 256>>>(X);
    k_tr_w<<<dim3(64, 64), tb>>>(Wq, 0, DMODEL, DMODEL);
    k_tr_w<<<dim3(4, 64),  tb>>>(Wk, 1, DMODEL, HDIM);
    k_tr_w<<<dim3(4, 64),  tb>>>(Wv, 2, DMODEL, HDIM);
    k_tr_w<<<dim3(64, 64), tb>>>(Wo, 3, DMODEL, DMODEL);

    k_qproj<<<dim3(DMODEL / 128, MROWS / 128), 256, SMEM_GEMM>>>();
    k_kv<<<dim3(1, MROWS / 128, 2), 256, SMEM_GEMM>>>();
    k_tr_v<<<dim3(HDIM / 32, SEQ / 32, BATCH), tb>>>();

    k_flash<<<dim3(SEQ / 128, BATCH * NHEAD), 256, SMEM_FLASH>>>();

    k_outproj<<<dim3(DMODEL / 128, MROWS / 128), 256, SMEM_GEMM>>>(out);
}

// round 5
// speedup vs baseline: 3.5527x; 1.0145x over previous
#include <cuda_runtime.h>
#include <cuda_bf16.h>
#include <cstdint>

#define BATCH 2
#define SEQ   2048
#define DMODEL 2048
#define NHEAD 16
#define HDIM  128
#define MROWS (BATCH * SEQ)
#define SCALE 0.08838834764831845f

typedef __nv_bfloat16 bf16;

// ------------------------- scratch (device globals) -------------------------
__device__ __align__(128) bf16 g_Xhi[(size_t)MROWS * DMODEL];
__device__ __align__(128) bf16 g_Xlo[(size_t)MROWS * DMODEL];
__device__ __align__(128) bf16 g_WqThi[(size_t)DMODEL * DMODEL];
__device__ __align__(128) bf16 g_WqTlo[(size_t)DMODEL * DMODEL];
__device__ __align__(128) bf16 g_WoThi[(size_t)DMODEL * DMODEL];
__device__ __align__(128) bf16 g_WoTlo[(size_t)DMODEL * DMODEL];
__device__ __align__(128) bf16 g_WkThi[(size_t)HDIM * DMODEL];
__device__ __align__(128) bf16 g_WkTlo[(size_t)HDIM * DMODEL];
__device__ __align__(128) bf16 g_WvThi[(size_t)HDIM * DMODEL];
__device__ __align__(128) bf16 g_WvTlo[(size_t)HDIM * DMODEL];
__device__ __align__(128) bf16 g_Qhi[(size_t)MROWS * DMODEL];   // pre-scaled by SCALE
__device__ __align__(128) bf16 g_Qlo[(size_t)MROWS * DMODEL];
__device__ __align__(128) bf16 g_Khi[(size_t)MROWS * HDIM];
__device__ __align__(128) bf16 g_Klo[(size_t)MROWS * HDIM];
__device__ __align__(128) bf16 g_VThi[(size_t)BATCH * HDIM * SEQ];
__device__ __align__(128) bf16 g_VTlo[(size_t)BATCH * HDIM * SEQ];
__device__ __align__(128) bf16 g_Hhi[(size_t)MROWS * DMODEL];
__device__ __align__(128) bf16 g_Hlo[(size_t)MROWS * DMODEL];

// ------------------------- PTX helpers --------------------------------------
__device__ __forceinline__ uint32_t cvta_s(const void* p) {
    uint32_t a;
    asm("{ .reg .u64 t; cvta.to.shared.u64 t, %1; cvt.u32.u64 %0, t; }"
        : "=r"(a) : "l"(p));
    return a;
}
__device__ __forceinline__ void cp16(uint32_t s, const void* g) {
    asm volatile("cp.async.cg.shared.global [%0], [%1], 16;" :: "r"(s), "l"(g));
}
__device__ __forceinline__ void ldsm4(uint32_t* r, uint32_t addr) {
    asm volatile("ldmatrix.sync.aligned.m8n8.x4.shared.b16 {%0,%1,%2,%3}, [%4];"
                 : "=r"(r[0]), "=r"(r[1]), "=r"(r[2]), "=r"(r[3]) : "r"(addr));
}
__device__ __forceinline__ void mma16816(float* c, const uint32_t* a, const uint32_t* b) {
    asm volatile(
        "mma.sync.aligned.m16n8k16.row.col.f32.bf16.bf16.f32 "
        "{%0,%1,%2,%3}, {%4,%5,%6,%7}, {%8,%9}, {%0,%1,%2,%3};"
        : "+f"(c[0]), "+f"(c[1]), "+f"(c[2]), "+f"(c[3])
        : "r"(a[0]), "r"(a[1]), "r"(a[2]), "r"(a[3]), "r"(b[0]), "r"(b[1]));
}
__device__ __forceinline__ void split1(float x, bf16& h, bf16& l) {
    h = __float2bfloat16(x);
    l = __float2bfloat16(x - __bfloat162float(h));
}
__device__ __forceinline__ uint32_t packh(bf16 a, bf16 b) {
    __nv_bfloat162 t; t.x = a; t.y = b;
    return *(uint32_t*)&t;
}

// ------------------------- 128x128 split-bf16 GEMM (small/narrow cases) ------
// C[row0:+128, col0:+128] = alpha * A @ B^T. mode 0: fp32 Cf; mode 1: split.
template<int STAGES>
__device__ __forceinline__ void gemm_tc(
    const bf16* __restrict__ Ahi, const bf16* __restrict__ Alo, int lda,
    const bf16* __restrict__ Bhi, const bf16* __restrict__ Blo, int ldb,
    int K, int row0, int col0, int mode, float alpha,
    float* __restrict__ Cf, bf16* __restrict__ Chi, bf16* __restrict__ Clo, int ldc)
{
    extern __shared__ char dsm[];
    const int tid = threadIdx.x, wid = tid >> 5, l = tid & 31;
    const int wm = (wid & 3) * 32;
    const int wn = (wid >> 2) * 64;
    const uint32_t sbase = cvta_s(dsm);
    const int n = K >> 6;

    float acc[2][8][4] = {};

    auto load_chunk = [&](int k) {
        uint32_t sb = sbase + (uint32_t)(k % STAGES) * 65536u;
        int k0 = k << 6;
        #pragma unroll
        for (int i = tid; i < 1024; i += 256) {
            int r = i >> 3, c = i & 7;
            uint32_t off = (uint32_t)(r * 128) + ((uint32_t)(c ^ (r & 7)) << 4);
            size_t ge = (size_t)(row0 + r) * lda + k0 + c * 8;
            cp16(sb + off, Ahi + ge);
            cp16(sb + 16384u + off, Alo + ge);
        }
        #pragma unroll
        for (int i = tid; i < 1024; i += 256) {
            int r = i >> 3, c = i & 7;
            uint32_t off = (uint32_t)(r * 128) + ((uint32_t)(c ^ (r & 7)) << 4);
            size_t ge = (size_t)(col0 + r) * ldb + k0 + c * 8;
            cp16(sb + 32768u + off, Bhi + ge);
            cp16(sb + 49152u + off, Blo + ge);
        }
        asm volatile("cp.async.commit_group;" ::: "memory");
    };

    for (int k = 0; k < STAGES - 1 && k < n; k++) load_chunk(k);

    const int at = l >> 3;
    const int arow = ((at & 1) << 3) + (l & 7);
    const uint32_t acolx = (uint32_t)((at >> 1) << 4);
    const int brow = (((l >> 4) & 1) << 3) + (l & 7);
    const uint32_t bcolx = (uint32_t)(((l >> 3) & 1) << 4);

    for (int k = 0; k < n; k++) {
        asm volatile("cp.async.wait_group %0;" :: "n"(STAGES - 2) : "memory");
        __syncthreads();
        int kp = k + STAGES - 1;
        if (kp < n) load_chunk(kp);
        else asm volatile("cp.async.commit_group;" ::: "memory");

        uint32_t sA = sbase + (uint32_t)(k % STAGES) * 65536u;
        uint32_t sB = sA + 32768u;
        #pragma unroll
        for (int ks = 0; ks < 4; ks++) {
            const uint32_t koff = (uint32_t)(ks << 5);
            uint32_t ah[2][4], al_[2][4];
            #pragma unroll
            for (int mi = 0; mi < 2; mi++) {
                int r = wm + mi * 16 + arow;
                uint32_t c = (koff + acolx) ^ ((uint32_t)(r & 7) << 4);
                ldsm4(ah[mi], sA + (uint32_t)(r * 128) + c);
                ldsm4(al_[mi], sA + 16384u + (uint32_t)(r * 128) + c);
            }
            uint32_t bh[4][4], bl_[4][4];
            #pragma unroll
            for (int nj = 0; nj < 4; nj++) {
                int r = wn + nj * 16 + brow;
                uint32_t c = (koff + bcolx) ^ ((uint32_t)(r & 7) << 4);
                ldsm4(bh[nj], sB + (uint32_t)(r * 128) + c);
                ldsm4(bl_[nj], sB + 16384u + (uint32_t)(r * 128) + c);
            }
            #pragma unroll
            for (int mi = 0; mi < 2; mi++)
                #pragma unroll
                for (int ni = 0; ni < 8; ni++) {
                    float* c = acc[mi][ni];
                    const uint32_t* bf = &bh[ni >> 1][(ni & 1) * 2];
                    const uint32_t* blf = &bl_[ni >> 1][(ni & 1) * 2];
                    mma16816(c, ah[mi], bf);
                    mma16816(c, ah[mi], blf);
                    mma16816(c, al_[mi], bf);
                }
        }
    }

    #pragma unroll
    for (int mi = 0; mi < 2; mi++) {
        #pragma unroll
        for (int ni = 0; ni < 8; ni++) {
            int r0r = row0 + wm + mi * 16 + (l >> 2);
            int col = col0 + wn + ni * 8 + (l & 3) * 2;
            float c0 = acc[mi][ni][0] * alpha, c1 = acc[mi][ni][1] * alpha;
            float c2 = acc[mi][ni][2] * alpha, c3 = acc[mi][ni][3] * alpha;
            if (mode == 0) {
                *(float2*)(Cf + (size_t)r0r * ldc + col) = make_float2(c0, c1);
                *(float2*)(Cf + (size_t)(r0r + 8) * ldc + col) = make_float2(c2, c3);
            } else {
                bf16 h0, l0, h1, l1, h2, l2, h3, l3;
                split1(c0, h0, l0); split1(c1, h1, l1);
                split1(c2, h2, l2); split1(c3, h3, l3);
                *(uint32_t*)(Chi + (size_t)r0r * ldc + col) = packh(h0, h1);
                *(uint32_t*)(Clo + (size_t)r0r * ldc + col) = packh(l0, l1);
                *(uint32_t*)(Chi + (size_t)(r0r + 8) * ldc + col) = packh(h2, h3);
                *(uint32_t*)(Clo + (size_t)(r0r + 8) * ldc + col) = packh(l2, l3);
            }
        }
    }
}

// ------------------------- 128x256 big-tile GEMM (warp tile 64x64) -----------
// 2 stages, BK=64. Stage: Ahi 16K | Alo 16K | Bhi 32K | Blo 32K = 96KB.
__device__ __forceinline__ void gemm_big(
    const bf16* __restrict__ Ahi, const bf16* __restrict__ Alo, int lda,
    const bf16* __restrict__ Bhi, const bf16* __restrict__ Blo, int ldb,
    int K, int row0, int col0, int mode, float alpha,
    float* __restrict__ Cf, bf16* __restrict__ Chi, bf16* __restrict__ Clo, int ldc)
{
    extern __shared__ char dsm[];
    const int tid = threadIdx.x, wid = tid >> 5, l = tid & 31;
    const int wm = (wid & 1) * 64;
    const int wn = (wid >> 1) * 64;
    const uint32_t sbase = cvta_s(dsm);
    const int n = K >> 6;

    float acc[4][8][4] = {};

    auto load_chunk = [&](int k) {
        uint32_t sb = sbase + (uint32_t)(k & 1) * 98304u;
        int k0 = k << 6;
        #pragma unroll
        for (int i = tid; i < 1024; i += 256) {           // A 128 rows
            int r = i >> 3, c = i & 7;
            uint32_t off = (uint32_t)(r * 128) + ((uint32_t)(c ^ (r & 7)) << 4);
            size_t ge = (size_t)(row0 + r) * lda + k0 + c * 8;
            cp16(sb + off, Ahi + ge);
            cp16(sb + 16384u + off, Alo + ge);
        }
        #pragma unroll
        for (int i = tid; i < 2048; i += 256) {           // B 256 rows
            int r = i >> 3, c = i & 7;
            uint32_t off = (uint32_t)(r * 128) + ((uint32_t)(c ^ (r & 7)) << 4);
            size_t ge = (size_t)(col0 + r) * ldb + k0 + c * 8;
            cp16(sb + 32768u + off, Bhi + ge);
            cp16(sb + 65536u + off, Blo + ge);
        }
        asm volatile("cp.async.commit_group;" ::: "memory");
    };

    load_chunk(0);

    const int at = l >> 3;
    const int arow = ((at & 1) << 3) + (l & 7);
    const uint32_t acolx = (uint32_t)((at >> 1) << 4);
    const int brow = (((l >> 4) & 1) << 3) + (l & 7);
    const uint32_t bcolx = (uint32_t)(((l >> 3) & 1) << 4);

    for (int k = 0; k < n; k++) {
        if (k + 1 < n) {
            load_chunk(k + 1);
            asm volatile("cp.async.wait_group 1;" ::: "memory");
        } else {
            asm volatile("cp.async.wait_group 0;" ::: "memory");
        }
        __syncthreads();

        uint32_t sA = sbase + (uint32_t)(k & 1) * 98304u;
        uint32_t sB = sA + 32768u;
        #pragma unroll
        for (int ks = 0; ks < 4; ks++) {
            const uint32_t koff = (uint32_t)(ks << 5);
            uint32_t bh[4][4], bl_[4][4];
            #pragma unroll
            for (int nj = 0; nj < 4; nj++) {
                int r = wn + nj * 16 + brow;
                uint32_t c = (koff + bcolx) ^ ((uint32_t)(r & 7) << 4);
                ldsm4(bh[nj], sB + (uint32_t)(r * 128) + c);
                ldsm4(bl_[nj], sB + 32768u + (uint32_t)(r * 128) + c);
            }
            #pragma unroll
            for (int mi = 0; mi < 4; mi++) {
                int r = wm + mi * 16 + arow;
                uint32_t c = (koff + acolx) ^ ((uint32_t)(r & 7) << 4);
                uint32_t ah[4], al_[4];
                ldsm4(ah, sA + (uint32_t)(r * 128) + c);
                ldsm4(al_, sA + 16384u + (uint32_t)(r * 128) + c);
                #pragma unroll
                for (int ni = 0; ni < 8; ni++) {
                    float* cc = acc[mi][ni];
                    const uint32_t* bf = &bh[ni >> 1][(ni & 1) * 2];
                    const uint32_t* blf = &bl_[ni >> 1][(ni & 1) * 2];
                    mma16816(cc, ah, bf);
                    mma16816(cc, ah, blf);
                    mma16816(cc, al_, bf);
                }
            }
        }
        __syncthreads();
    }

    #pragma unroll
    for (int mi = 0; mi < 4; mi++) {
        #pragma unroll
        for (int ni = 0; ni < 8; ni++) {
            int r0r = row0 + wm + mi * 16 + (l >> 2);
            int col = col0 + wn + ni * 8 + (l & 3) * 2;
            float c0 = acc[mi][ni][0] * alpha, c1 = acc[mi][ni][1] * alpha;
            float c2 = acc[mi][ni][2] * alpha, c3 = acc[mi][ni][3] * alpha;
            if (mode == 0) {
                *(float2*)(Cf + (size_t)r0r * ldc + col) = make_float2(c0, c1);
                *(float2*)(Cf + (size_t)(r0r + 8) * ldc + col) = make_float2(c2, c3);
            } else {
                bf16 h0, l0, h1, l1, h2, l2, h3, l3;
                split1(c0, h0, l0); split1(c1, h1, l1);
                split1(c2, h2, l2); split1(c3, h3, l3);
                *(uint32_t*)(Chi + (size_t)r0r * ldc + col) = packh(h0, h1);
                *(uint32_t*)(Clo + (size_t)r0r * ldc + col) = packh(l0, l1);
                *(uint32_t*)(Chi + (size_t)(r0r + 8) * ldc + col) = packh(h2, h3);
                *(uint32_t*)(Clo + (size_t)(r0r + 8) * ldc + col) = packh(l2, l3);
            }
        }
    }
}

// ------------------------- fused flash attention -----------------------------
// Grid (SEQ/128, BATCH*NHEAD). 256 thr, 8 warps x m16 rows. K/V chunks of 64.
// Q pre-scaled by SCALE. Q fragments hoisted into registers (loop-invariant).
#define FSTAGE 65536u
#define SMEM_FLASH 196608

__global__ __launch_bounds__(256, 1) void k_flash() {
    extern __shared__ char dsm[];
    const int tid = threadIdx.x, wid = tid >> 5, l = tid & 31;
    const int p = blockIdx.y, b = p >> 4, h = p & 15;
    const int q0 = blockIdx.x * 128;
    const bf16* Qh = g_Qhi + (size_t)b * SEQ * DMODEL + (size_t)h * HDIM;
    const bf16* Ql = g_Qlo + (size_t)b * SEQ * DMODEL + (size_t)h * HDIM;
    const bf16* Kh = g_Khi + (size_t)b * SEQ * HDIM;
    const bf16* Kl = g_Klo + (size_t)b * SEQ * HDIM;
    const bf16* Vh = g_VThi + (size_t)b * HDIM * SEQ;
    const bf16* Vl = g_VTlo + (size_t)b * HDIM * SEQ;
    const uint32_t sb = cvta_s(dsm);
    const uint32_t sQh = sb, sQl = sb + 32768u, sSt = sb + 65536u;

    #pragma unroll
    for (int i = tid; i < 2048; i += 256) {
        int r = i >> 4, c = i & 15;
        uint32_t off = (uint32_t)(r * 256) + (((uint32_t)(c * 16)) ^ ((uint32_t)(r & 7) << 4));
        size_t ge = (size_t)(q0 + r) * DMODEL + c * 8;
        cp16(sQh + off, Qh + ge);
        cp16(sQl + off, Ql + ge);
    }
    auto loadkv = [&](int kc) {
        uint32_t s = sSt + (uint32_t)(kc & 1) * FSTAGE;
        int key0 = kc * 64;
        #pragma unroll
        for (int i = tid; i < 1024; i += 256) {   // K: 64 rows x 256B
            int r = i >> 4, c = i & 15;
            uint32_t off = (uint32_t)(r * 256) + (((uint32_t)(c * 16)) ^ ((uint32_t)(r & 7) << 4));
            size_t ge = (size_t)(key0 + r) * HDIM + c * 8;
            cp16(s + off, Kh + ge);
            cp16(s + 16384u + off, Kl + ge);
        }
        #pragma unroll
        for (int i = tid; i < 1024; i += 256) {   // V^T: 128 rows x 128B
            int r = i >> 3, c = i & 7;
            uint32_t off = (uint32_t)(r * 128) + (((uint32_t)(c * 16)) ^ ((uint32_t)(r & 7) << 4));
            size_t ge = (size_t)r * SEQ + key0 + c * 8;
            cp16(s + 32768u + off, Vh + ge);
            cp16(s + 49152u + off, Vl + ge);
        }
        asm volatile("cp.async.commit_group;" ::: "memory");
    };
    loadkv(0);

    const int at = l >> 3;
    const int arow = ((at & 1) << 3) + (l & 7);
    const uint32_t acolx = (uint32_t)((at >> 1) << 4);
    const int brow = (((l >> 4) & 1) << 3) + (l & 7);
    const uint32_t bcolx = (uint32_t)(((l >> 3) & 1) << 4);
    const int m0 = wid * 16;

    // hoist Q fragments (invariant across key chunks)
    asm volatile("cp.async.wait_group 0;" ::: "memory");
    __syncthreads();
    uint32_t qh[8][4], ql[8][4];
    {
        int r = m0 + arow;
        uint32_t rowoff = (uint32_t)(r * 256);
        #pragma unroll
        for (int ks = 0; ks < 8; ks++) {
            uint32_t c = ((uint32_t)(ks << 5) + acolx) ^ ((uint32_t)(r & 7) << 4);
            ldsm4(qh[ks], sQh + rowoff + c);
            ldsm4(ql[ks], sQl + rowoff + c);
        }
    }

    float oacc[16][4] = {};
    float mrow0 = -1e30f, mrow1 = -1e30f, lsum0 = 0.f, lsum1 = 0.f;

    for (int kc = 0; kc < SEQ / 64; kc++) {
        if (kc + 1 < SEQ / 64) {
            loadkv(kc + 1);
            asm volatile("cp.async.wait_group 1;" ::: "memory");
        } else {
            asm volatile("cp.async.wait_group 0;" ::: "memory");
        }
        __syncthreads();
        uint32_t s = sSt + (uint32_t)(kc & 1) * FSTAGE;
        uint32_t sKh = s, sKl = s + 16384u, sVh = s + 32768u, sVl = s + 49152u;

        // S = Q @ K^T  (m16 x n64, k=128)
        float sacc[8][4] = {};
        #pragma unroll
        for (int ks = 0; ks < 8; ks++) {
            const uint32_t koff = (uint32_t)(ks << 5);
            #pragma unroll
            for (int nj = 0; nj < 4; nj++) {
                int rr = nj * 16 + brow;
                uint32_t cc = (koff + bcolx) ^ ((uint32_t)(rr & 7) << 4);
                uint32_t kh4[4], kl4[4];
                ldsm4(kh4, sKh + (uint32_t)(rr * 256) + cc);
                ldsm4(kl4, sKl + (uint32_t)(rr * 256) + cc);
                #pragma unroll
                for (int t2 = 0; t2 < 2; t2++) {
                    float* c = sacc[nj * 2 + t2];
                    mma16816(c, qh[ks], &kh4[t2 * 2]);
                    mma16816(c, qh[ks], &kl4[t2 * 2]);
                    mma16816(c, ql[ks], &kh4[t2 * 2]);
                }
            }
        }

        // online softmax
        float mx0 = -1e30f, mx1 = -1e30f;
        #pragma unroll
        for (int ni = 0; ni < 8; ni++) {
            mx0 = fmaxf(mx0, fmaxf(sacc[ni][0], sacc[ni][1]));
            mx1 = fmaxf(mx1, fmaxf(sacc[ni][2], sacc[ni][3]));
        }
        mx0 = fmaxf(mx0, __shfl_xor_sync(0xffffffffu, mx0, 1));
        mx0 = fmaxf(mx0, __shfl_xor_sync(0xffffffffu, mx0, 2));
        mx1 = fmaxf(mx1, __shfl_xor_sync(0xffffffffu, mx1, 1));
        mx1 = fmaxf(mx1, __shfl_xor_sync(0xffffffffu, mx1, 2));
        float mn0 = fmaxf(mrow0, mx0), mn1 = fmaxf(mrow1, mx1);
        float a0 = __expf(mrow0 - mn0), a1 = __expf(mrow1 - mn1);
        mrow0 = mn0; mrow1 = mn1;
        float ps0 = 0.f, ps1 = 0.f;
        #pragma unroll
        for (int ni = 0; ni < 8; ni++) {
            sacc[ni][0] = __expf(sacc[ni][0] - mn0);
            sacc[ni][1] = __expf(sacc[ni][1] - mn0);
            sacc[ni][2] = __expf(sacc[ni][2] - mn1);
            sacc[ni][3] = __expf(sacc[ni][3] - mn1);
            ps0 += sacc[ni][0] + sacc[ni][1];
            ps1 += sacc[ni][2] + sacc[ni][3];
        }
        lsum0 = lsum0 * a0 + ps0;
        lsum1 = lsum1 * a1 + ps1;
        #pragma unroll
        for (int ni = 0; ni < 16; ni++) {
            oacc[ni][0] *= a0; oacc[ni][1] *= a0;
            oacc[ni][2] *= a1; oacc[ni][3] *= a1;
        }

        // O += P @ V
        #pragma unroll
        for (int j = 0; j < 4; j++) {
            uint32_t phi[4], plo[4];
            #pragma unroll
            for (int t2 = 0; t2 < 2; t2++) {
                float x0 = sacc[2 * j + t2][0], x1 = sacc[2 * j + t2][1];
                float x2 = sacc[2 * j + t2][2], x3 = sacc[2 * j + t2][3];
                bf16 h0, l0, h1, l1, h2, l2, h3, l3;
                split1(x0, h0, l0); split1(x1, h1, l1);
                split1(x2, h2, l2); split1(x3, h3, l3);
                phi[t2 * 2 + 0] = packh(h0, h1);
                phi[t2 * 2 + 1] = packh(h2, h3);
                plo[t2 * 2 + 0] = packh(l0, l1);
                plo[t2 * 2 + 1] = packh(l2, l3);
            }
            #pragma unroll
            for (int nj = 0; nj < 8; nj++) {
                int rr = nj * 16 + brow;
                uint32_t cc = ((uint32_t)(j << 5) + bcolx) ^ ((uint32_t)(rr & 7) << 4);
                uint32_t vh4[4], vl4[4];
                ldsm4(vh4, sVh + (uint32_t)(rr * 128) + cc);
                ldsm4(vl4, sVl + (uint32_t)(rr * 128) + cc);
                #pragma unroll
                for (int t2 = 0; t2 < 2; t2++) {
                    float* o = oacc[nj * 2 + t2];
                    mma16816(o, phi, &vh4[t2 * 2]);
                    mma16816(o, phi, &vl4[t2 * 2]);
                    mma16816(o, plo, &vh4[t2 * 2]);
                }
            }
        }
        __syncthreads();
    }

    // epilogue
    lsum0 += __shfl_xor_sync(0xffffffffu, lsum0, 1);
    lsum0 += __shfl_xor_sync(0xffffffffu, lsum0, 2);
    lsum1 += __shfl_xor_sync(0xffffffffu, lsum1, 1);
    lsum1 += __shfl_xor_sync(0xffffffffu, lsum1, 2);
    float inv0 = 1.0f / lsum0, inv1 = 1.0f / lsum1;
    bf16* Hh = g_Hhi + (size_t)b * SEQ * DMODEL + (size_t)h * HDIM;
    bf16* Hl = g_Hlo + (size_t)b * SEQ * DMODEL + (size_t)h * HDIM;
    const int r0r = q0 + m0 + (l >> 2);
    const int colb = (l & 3) * 2;
    #pragma unroll
    for (int nj = 0; nj < 16; nj++) {
        float x0 = oacc[nj][0] * inv0, x1 = oacc[nj][1] * inv0;
        float x2 = oacc[nj][2] * inv1, x3 = oacc[nj][3] * inv1;
        bf16 h0, l0, h1, l1, h2, l2, h3, l3;
        split1(x0, h0, l0); split1(x1, h1, l1);
        split1(x2, h2, l2); split1(x3, h3, l3);
        int col = nj * 8 + colb;
        *(uint32_t*)(Hh + (size_t)r0r * DMODEL + col) = packh(h0, h1);
        *(uint32_t*)(Hl + (size_t)r0r * DMODEL + col) = packh(l0, l1);
        *(uint32_t*)(Hh + (size_t)(r0r + 8) * DMODEL + col) = packh(h2, h3);
        *(uint32_t*)(Hl + (size_t)(r0r + 8) * DMODEL + col) = packh(l2, l3);
    }
}

// ------------------------- fused prep: split X + transpose-split weights -----
__device__ __forceinline__ void tr_split_body(const float* __restrict__ src,
                                              bf16* __restrict__ dhi,
                                              bf16* __restrict__ dlo,
                                              int R, int C, int bx, int by) {
    __shared__ float t[32][33];
    int r0 = by * 32, c0 = bx * 32;
    int tx = threadIdx.x & 31, ty = threadIdx.x >> 5;  // 32 x 8
    #pragma unroll
    for (int j = 0; j < 4; j++)
        t[ty + j * 8][tx] = src[(size_t)(r0 + ty + j * 8) * C + c0 + tx];
    __syncthreads();
    #pragma unroll
    for (int j = 0; j < 4; j++) {
        float v = t[tx][ty + j * 8];
        bf16 h, l;
        split1(v, h, l);
        size_t o = (size_t)(c0 + ty + j * 8) * R + r0 + tx;
        dhi[o] = h;
        dlo[o] = l;
    }
}

__global__ __launch_bounds__(256) void k_prep(const float* __restrict__ X,
                                              const float* __restrict__ Wq,
                                              const float* __restrict__ Wk,
                                              const float* __restrict__ Wv,
                                              const float* __restrict__ Wo) {
    int z = blockIdx.z;
    if (z == 0) { tr_split_body(Wq, g_WqThi, g_WqTlo, DMODEL, DMODEL, blockIdx.x, blockIdx.y); return; }
    if (z == 1) { tr_split_body(Wo, g_WoThi, g_WoTlo, DMODEL, DMODEL, blockIdx.x, blockIdx.y); return; }
    if (z == 2) { if (blockIdx.x < 4) tr_split_body(Wk, g_WkThi, g_WkTlo, DMODEL, HDIM, blockIdx.x, blockIdx.y); return; }
    if (z == 3) { if (blockIdx.x < 4) tr_split_body(Wv, g_WvThi, g_WvTlo, DMODEL, HDIM, blockIdx.x, blockIdx.y); return; }
    // z = 4,5: split X
    size_t bid = (size_t)(z - 4) * 4096 + blockIdx.y * 64 + blockIdx.x;
    size_t i = (bid * 256 + threadIdx.x) * 4;
    if (i >= (size_t)MROWS * DMODEL) return;
    float4 v = *(const float4*)(X + i);
    bf16 h0, l0, h1, l1, h2, l2, h3, l3;
    split1(v.x, h0, l0); split1(v.y, h1, l1);
    split1(v.z, h2, l2); split1(v.w, h3, l3);
    *(uint32_t*)(g_Xhi + i) = packh(h0, h1);
    *(uint32_t*)(g_Xhi + i + 2) = packh(h2, h3);
    *(uint32_t*)(g_Xlo + i) = packh(l0, l1);
    *(uint32_t*)(g_Xlo + i + 2) = packh(l2, l3);
}

// ------------------------- GEMM wrapper kernels -----------------------------
__global__ __launch_bounds__(256, 1) void k_qproj() {
    gemm_big(g_Xhi, g_Xlo, DMODEL, g_WqThi, g_WqTlo, DMODEL,
             DMODEL, blockIdx.y * 128, blockIdx.x * 256,
             1, SCALE, nullptr, g_Qhi, g_Qlo, DMODEL);
}

// z=0: K = X @ WkT (tokens x 128). z=1: V^T = WvT @ X^T (128 x tokens)
__global__ __launch_bounds__(256, 1) void k_kvT() {
    if (blockIdx.z == 0) {
        gemm_tc<3>(g_Xhi, g_Xlo, DMODEL, g_WkThi, g_WkTlo, DMODEL,
                   DMODEL, blockIdx.y * 128, 0,
                   1, 1.0f, nullptr, g_Khi, g_Klo, HDIM);
    } else {
        int t0 = blockIdx.y * 128;             // global token block
        int b = t0 / SEQ, tl = t0 % SEQ;
        gemm_tc<3>(g_WvThi, g_WvTlo, DMODEL,
                   g_Xhi + (size_t)t0 * DMODEL, g_Xlo + (size_t)t0 * DMODEL, DMODEL,
                   DMODEL, 0, 0,
                   1, 1.0f, nullptr,
                   g_VThi + (size_t)b * HDIM * SEQ + tl,
                   g_VTlo + (size_t)b * HDIM * SEQ + tl, SEQ);
    }
}

__global__ __launch_bounds__(256, 1) void k_outproj(float* __restrict__ out) {
    gemm_big(g_Hhi, g_Hlo, DMODEL, g_WoThi, g_WoTlo, DMODEL,
             DMODEL, blockIdx.y * 128, blockIdx.x * 256,
             0, 1.0f, out, nullptr, nullptr, DMODEL);
}

// ------------------------- launch -------------------------------------------
#define SMEM_GEMM 196608

extern "C" void kernel_launch(void* const* d_in, const int* in_sizes, int n_in,
                              void* d_out, int out_size) {
    const float* X  = (const float*)d_in[0];
    const float* Wq = (const float*)d_in[1];
    const float* Wk = (const float*)d_in[2];
    const float* Wv = (const float*)d_in[3];
    const float* Wo = (const float*)d_in[4];
    float* out = (float*)d_out;

    static int attr_done = 0;
    if (!attr_done) {
        attr_done = 1;
        cudaFuncSetAttribute(k_qproj,   cudaFuncAttributeMaxDynamicSharedMemorySize, SMEM_GEMM);
        cudaFuncSetAttribute(k_kvT,     cudaFuncAttributeMaxDynamicSharedMemorySize, SMEM_GEMM);
        cudaFuncSetAttribute(k_outproj, cudaFuncAttributeMaxDynamicSharedMemorySize, SMEM_GEMM);
        cudaFuncSetAttribute(k_flash,   cudaFuncAttributeMaxDynamicSharedMemorySize, SMEM_FLASH);
    }

    k_prep<<<dim3(64, 64, 6), 256>>>(X, Wq, Wk, Wv, Wo);
    k_qproj<<<dim3(DMODEL / 256, MROWS / 128), 256, SMEM_GEMM>>>();
    k_kvT<<<dim3(1, MROWS / 128, 2), 256, SMEM_GEMM>>>();
    k_flash<<<dim3(SEQ / 128, BATCH * NHEAD), 256, SMEM_FLASH>>>();
    k_outproj<<<dim3(DMODEL / 256, MROWS / 128), 256, SMEM_GEMM>>>(out);
}

// round 6
// speedup vs baseline: 3.9849x; 1.1217x over previous
#include <cuda_runtime.h>
#include <cuda_bf16.h>
#include <cstdint>

#define BATCH 2
#define SEQ   2048
#define DMODEL 2048
#define NHEAD 16
#define HDIM  128
#define MROWS (BATCH * SEQ)
#define SCALE 0.08838834764831845f

typedef __nv_bfloat16 bf16;

// ------------------------- scratch (device globals) -------------------------
__device__ __align__(128) bf16 g_Xhi[(size_t)MROWS * DMODEL];
__device__ __align__(128) bf16 g_Xlo[(size_t)MROWS * DMODEL];
__device__ __align__(128) bf16 g_WqThi[(size_t)DMODEL * DMODEL];
__device__ __align__(128) bf16 g_WqTlo[(size_t)DMODEL * DMODEL];
__device__ __align__(128) bf16 g_WoThi[(size_t)DMODEL * DMODEL];
__device__ __align__(128) bf16 g_WoTlo[(size_t)DMODEL * DMODEL];
__device__ __align__(128) bf16 g_WkThi[(size_t)HDIM * DMODEL];
__device__ __align__(128) bf16 g_WkTlo[(size_t)HDIM * DMODEL];
__device__ __align__(128) bf16 g_WvThi[(size_t)HDIM * DMODEL];
__device__ __align__(128) bf16 g_WvTlo[(size_t)HDIM * DMODEL];
__device__ __align__(128) bf16 g_Qhi[(size_t)MROWS * DMODEL];   // pre-scaled by SCALE
__device__ __align__(128) bf16 g_Qlo[(size_t)MROWS * DMODEL];
__device__ __align__(128) bf16 g_Khi[(size_t)MROWS * HDIM];
__device__ __align__(128) bf16 g_Klo[(size_t)MROWS * HDIM];
__device__ __align__(128) bf16 g_VThi[(size_t)BATCH * HDIM * SEQ];
__device__ __align__(128) bf16 g_VTlo[(size_t)BATCH * HDIM * SEQ];
__device__ __align__(128) bf16 g_Hhi[(size_t)MROWS * DMODEL];
__device__ __align__(128) bf16 g_Hlo[(size_t)MROWS * DMODEL];

// ------------------------- PTX helpers --------------------------------------
__device__ __forceinline__ uint32_t cvta_s(const void* p) {
    uint32_t a;
    asm("{ .reg .u64 t; cvta.to.shared.u64 t, %1; cvt.u32.u64 %0, t; }"
        : "=r"(a) : "l"(p));
    return a;
}
__device__ __forceinline__ void cp16(uint32_t s, const void* g) {
    asm volatile("cp.async.cg.shared.global [%0], [%1], 16;" :: "r"(s), "l"(g));
}
__device__ __forceinline__ void ldsm4(uint32_t* r, uint32_t addr) {
    asm volatile("ldmatrix.sync.aligned.m8n8.x4.shared.b16 {%0,%1,%2,%3}, [%4];"
                 : "=r"(r[0]), "=r"(r[1]), "=r"(r[2]), "=r"(r[3]) : "r"(addr));
}
__device__ __forceinline__ void mma16816(float* c, const uint32_t* a, const uint32_t* b) {
    asm volatile(
        "mma.sync.aligned.m16n8k16.row.col.f32.bf16.bf16.f32 "
        "{%0,%1,%2,%3}, {%4,%5,%6,%7}, {%8,%9}, {%0,%1,%2,%3};"
        : "+f"(c[0]), "+f"(c[1]), "+f"(c[2]), "+f"(c[3])
        : "r"(a[0]), "r"(a[1]), "r"(a[2]), "r"(a[3]), "r"(b[0]), "r"(b[1]));
}
__device__ __forceinline__ void split1(float x, bf16& h, bf16& l) {
    h = __float2bfloat16(x);
    l = __float2bfloat16(x - __bfloat162float(h));
}
__device__ __forceinline__ uint32_t packh(bf16 a, bf16 b) {
    __nv_bfloat162 t; t.x = a; t.y = b;
    return *(uint32_t*)&t;
}

// ------------------------- 64x128-tile split-bf16 GEMM (2 CTAs/SM) -----------
// C[row0:+64, col0:+128] = alpha * A @ B^T. K-major hi/lo pairs.
// 128 threads, 4 warps (warp tile 32x64). 2 stages x 48KB = 96KB smem.
// Stage: Ahi 8K | Alo 8K | Bhi 16K | Blo 16K.
__device__ __forceinline__ void gemm64(
    const bf16* __restrict__ Ahi, const bf16* __restrict__ Alo, int lda,
    const bf16* __restrict__ Bhi, const bf16* __restrict__ Blo, int ldb,
    int K, int row0, int col0, int mode, float alpha,
    float* __restrict__ Cf, bf16* __restrict__ Chi, bf16* __restrict__ Clo, int ldc)
{
    extern __shared__ char dsm[];
    const int tid = threadIdx.x, wid = tid >> 5, l = tid & 31;
    const int wm = (wid & 1) * 32;
    const int wn = (wid >> 1) * 64;
    const uint32_t sbase = cvta_s(dsm);
    const int n = K >> 6;

    float acc[2][8][4] = {};

    auto load_chunk = [&](int k) {
        uint32_t sb = sbase + (uint32_t)(k & 1) * 49152u;
        int k0 = k << 6;
        #pragma unroll
        for (int i = tid; i < 512; i += 128) {            // A: 64 rows x 8x16B
            int r = i >> 3, c = i & 7;
            uint32_t off = (uint32_t)(r * 128) + ((uint32_t)(c ^ (r & 7)) << 4);
            size_t ge = (size_t)(row0 + r) * lda + k0 + c * 8;
            cp16(sb + off, Ahi + ge);
            cp16(sb + 8192u + off, Alo + ge);
        }
        #pragma unroll
        for (int i = tid; i < 1024; i += 128) {           // B: 128 rows
            int r = i >> 3, c = i & 7;
            uint32_t off = (uint32_t)(r * 128) + ((uint32_t)(c ^ (r & 7)) << 4);
            size_t ge = (size_t)(col0 + r) * ldb + k0 + c * 8;
            cp16(sb + 16384u + off, Bhi + ge);
            cp16(sb + 32768u + off, Blo + ge);
        }
        asm volatile("cp.async.commit_group;" ::: "memory");
    };

    load_chunk(0);

    const int at = l >> 3;
    const int arow = ((at & 1) << 3) + (l & 7);
    const uint32_t acolx = (uint32_t)((at >> 1) << 4);
    const int brow = (((l >> 4) & 1) << 3) + (l & 7);
    const uint32_t bcolx = (uint32_t)(((l >> 3) & 1) << 4);

    for (int k = 0; k < n; k++) {
        if (k + 1 < n) {
            load_chunk(k + 1);
            asm volatile("cp.async.wait_group 1;" ::: "memory");
        } else {
            asm volatile("cp.async.wait_group 0;" ::: "memory");
        }
        __syncthreads();

        uint32_t sA = sbase + (uint32_t)(k & 1) * 49152u;
        uint32_t sB = sA + 16384u;
        #pragma unroll
        for (int ks = 0; ks < 4; ks++) {
            const uint32_t koff = (uint32_t)(ks << 5);
            uint32_t bh[4][4], bl_[4][4];
            #pragma unroll
            for (int nj = 0; nj < 4; nj++) {
                int r = wn + nj * 16 + brow;
                uint32_t c = (koff + bcolx) ^ ((uint32_t)(r & 7) << 4);
                ldsm4(bh[nj], sB + (uint32_t)(r * 128) + c);
                ldsm4(bl_[nj], sB + 16384u + (uint32_t)(r * 128) + c);
            }
            #pragma unroll
            for (int mi = 0; mi < 2; mi++) {
                int r = wm + mi * 16 + arow;
                uint32_t c = (koff + acolx) ^ ((uint32_t)(r & 7) << 4);
                uint32_t ah[4], al_[4];
                ldsm4(ah, sA + (uint32_t)(r * 128) + c);
                ldsm4(al_, sA + 8192u + (uint32_t)(r * 128) + c);
                #pragma unroll
                for (int ni = 0; ni < 8; ni++) {
                    float* cc = acc[mi][ni];
                    const uint32_t* bf = &bh[ni >> 1][(ni & 1) * 2];
                    const uint32_t* blf = &bl_[ni >> 1][(ni & 1) * 2];
                    mma16816(cc, ah, bf);
                    mma16816(cc, ah, blf);
                    mma16816(cc, al_, bf);
                }
            }
        }
        __syncthreads();
    }

    #pragma unroll
    for (int mi = 0; mi < 2; mi++) {
        #pragma unroll
        for (int ni = 0; ni < 8; ni++) {
            int r0r = row0 + wm + mi * 16 + (l >> 2);
            int col = col0 + wn + ni * 8 + (l & 3) * 2;
            float c0 = acc[mi][ni][0] * alpha, c1 = acc[mi][ni][1] * alpha;
            float c2 = acc[mi][ni][2] * alpha, c3 = acc[mi][ni][3] * alpha;
            if (mode == 0) {
                *(float2*)(Cf + (size_t)r0r * ldc + col) = make_float2(c0, c1);
                *(float2*)(Cf + (size_t)(r0r + 8) * ldc + col) = make_float2(c2, c3);
            } else {
                bf16 h0, l0, h1, l1, h2, l2, h3, l3;
                split1(c0, h0, l0); split1(c1, h1, l1);
                split1(c2, h2, l2); split1(c3, h3, l3);
                *(uint32_t*)(Chi + (size_t)r0r * ldc + col) = packh(h0, h1);
                *(uint32_t*)(Clo + (size_t)r0r * ldc + col) = packh(l0, l1);
                *(uint32_t*)(Chi + (size_t)(r0r + 8) * ldc + col) = packh(h2, h3);
                *(uint32_t*)(Clo + (size_t)(r0r + 8) * ldc + col) = packh(l2, l3);
            }
        }
    }
}

// ------------------------- fused flash attention (2 CTAs/SM) -----------------
// Grid (SEQ/64, BATCH*NHEAD). 128 thr, 4 warps x m16 rows. Key chunk 64.
// Single KV buffer; cross-CTA overlap hides load latency.
// SMEM: Qhi 16K | Qlo 16K | Khi 16K | Kl 16K | Vhi 16K | Vlo 16K = 96KB.
#define SMEM_FLASH 98304

__global__ __launch_bounds__(128, 2) void k_flash() {
    extern __shared__ char dsm[];
    const int tid = threadIdx.x, wid = tid >> 5, l = tid & 31;
    const int p = blockIdx.y, b = p >> 4, h = p & 15;
    const int q0 = blockIdx.x * 64;
    const bf16* Qh = g_Qhi + (size_t)b * SEQ * DMODEL + (size_t)h * HDIM;
    const bf16* Ql = g_Qlo + (size_t)b * SEQ * DMODEL + (size_t)h * HDIM;
    const bf16* Kh = g_Khi + (size_t)b * SEQ * HDIM;
    const bf16* Kl = g_Klo + (size_t)b * SEQ * HDIM;
    const bf16* Vh = g_VThi + (size_t)b * HDIM * SEQ;
    const bf16* Vl = g_VTlo + (size_t)b * HDIM * SEQ;
    const uint32_t sb = cvta_s(dsm);
    const uint32_t sQh = sb, sQl = sb + 16384u;
    const uint32_t sKh = sb + 32768u, sKl = sb + 49152u;
    const uint32_t sVh = sb + 65536u, sVl = sb + 81920u;

    // Q tile: 64 rows x 256B (hi/lo)
    #pragma unroll
    for (int i = tid; i < 1024; i += 128) {
        int r = i >> 4, c = i & 15;
        uint32_t off = (uint32_t)(r * 256) + (((uint32_t)(c * 16)) ^ ((uint32_t)(r & 7) << 4));
        size_t ge = (size_t)(q0 + r) * DMODEL + c * 8;
        cp16(sQh + off, Qh + ge);
        cp16(sQl + off, Ql + ge);
    }
    auto loadkv = [&](int kc) {
        int key0 = kc * 64;
        #pragma unroll
        for (int i = tid; i < 1024; i += 128) {   // K: 64 rows x 256B
            int r = i >> 4, c = i & 15;
            uint32_t off = (uint32_t)(r * 256) + (((uint32_t)(c * 16)) ^ ((uint32_t)(r & 7) << 4));
            size_t ge = (size_t)(key0 + r) * HDIM + c * 8;
            cp16(sKh + off, Kh + ge);
            cp16(sKl + off, Kl + ge);
        }
        #pragma unroll
        for (int i = tid; i < 1024; i += 128) {   // V^T: 128 rows x 128B
            int r = i >> 3, c = i & 7;
            uint32_t off = (uint32_t)(r * 128) + (((uint32_t)(c * 16)) ^ ((uint32_t)(r & 7) << 4));
            size_t ge = (size_t)r * SEQ + key0 + c * 8;
            cp16(sVh + off, Vh + ge);
            cp16(sVl + off, Vl + ge);
        }
        asm volatile("cp.async.commit_group;" ::: "memory");
    };
    loadkv(0);   // commits Q + KV0 together
    asm volatile("cp.async.wait_group 0;" ::: "memory");
    __syncthreads();

    const int at = l >> 3;
    const int arow = ((at & 1) << 3) + (l & 7);
    const uint32_t acolx = (uint32_t)((at >> 1) << 4);
    const int brow = (((l >> 4) & 1) << 3) + (l & 7);
    const uint32_t bcolx = (uint32_t)(((l >> 3) & 1) << 4);
    const int m0 = wid * 16;

    // hoist Q fragments (loop-invariant)
    uint32_t qh[8][4], ql[8][4];
    {
        int r = m0 + arow;
        uint32_t rowoff = (uint32_t)(r * 256);
        #pragma unroll
        for (int ks = 0; ks < 8; ks++) {
            uint32_t c = ((uint32_t)(ks << 5) + acolx) ^ ((uint32_t)(r & 7) << 4);
            ldsm4(qh[ks], sQh + rowoff + c);
            ldsm4(ql[ks], sQl + rowoff + c);
        }
    }

    float oacc[16][4] = {};
    float mrow0 = -1e30f, mrow1 = -1e30f, lsum0 = 0.f, lsum1 = 0.f;

    for (int kc = 0; kc < SEQ / 64; kc++) {
        // S = Q @ K^T  (m16 x n64, k=128)
        float sacc[8][4] = {};
        #pragma unroll
        for (int ks = 0; ks < 8; ks++) {
            const uint32_t koff = (uint32_t)(ks << 5);
            #pragma unroll
            for (int nj = 0; nj < 4; nj++) {
                int rr = nj * 16 + brow;
                uint32_t cc = (koff + bcolx) ^ ((uint32_t)(rr & 7) << 4);
                uint32_t kh4[4], kl4[4];
                ldsm4(kh4, sKh + (uint32_t)(rr * 256) + cc);
                ldsm4(kl4, sKl + (uint32_t)(rr * 256) + cc);
                #pragma unroll
                for (int t2 = 0; t2 < 2; t2++) {
                    float* c = sacc[nj * 2 + t2];
                    mma16816(c, qh[ks], &kh4[t2 * 2]);
                    mma16816(c, qh[ks], &kl4[t2 * 2]);
                    mma16816(c, ql[ks], &kh4[t2 * 2]);
                }
            }
        }

        // online softmax (quad of 4 lanes owns rows l/4 and l/4+8)
        float mx0 = -1e30f, mx1 = -1e30f;
        #pragma unroll
        for (int ni = 0; ni < 8; ni++) {
            mx0 = fmaxf(mx0, fmaxf(sacc[ni][0], sacc[ni][1]));
            mx1 = fmaxf(mx1, fmaxf(sacc[ni][2], sacc[ni][3]));
        }
        mx0 = fmaxf(mx0, __shfl_xor_sync(0xffffffffu, mx0, 1));
        mx0 = fmaxf(mx0, __shfl_xor_sync(0xffffffffu, mx0, 2));
        mx1 = fmaxf(mx1, __shfl_xor_sync(0xffffffffu, mx1, 1));
        mx1 = fmaxf(mx1, __shfl_xor_sync(0xffffffffu, mx1, 2));
        float mn0 = fmaxf(mrow0, mx0), mn1 = fmaxf(mrow1, mx1);
        float a0 = __expf(mrow0 - mn0), a1 = __expf(mrow1 - mn1);
        mrow0 = mn0; mrow1 = mn1;
        float ps0 = 0.f, ps1 = 0.f;
        #pragma unroll
        for (int ni = 0; ni < 8; ni++) {
            sacc[ni][0] = __expf(sacc[ni][0] - mn0);
            sacc[ni][1] = __expf(sacc[ni][1] - mn0);
            sacc[ni][2] = __expf(sacc[ni][2] - mn1);
            sacc[ni][3] = __expf(sacc[ni][3] - mn1);
            ps0 += sacc[ni][0] + sacc[ni][1];
            ps1 += sacc[ni][2] + sacc[ni][3];
        }
        lsum0 = lsum0 * a0 + ps0;
        lsum1 = lsum1 * a1 + ps1;
        #pragma unroll
        for (int ni = 0; ni < 16; ni++) {
            oacc[ni][0] *= a0; oacc[ni][1] *= a0;
            oacc[ni][2] *= a1; oacc[ni][3] *= a1;
        }

        // O += P @ V
        #pragma unroll
        for (int j = 0; j < 4; j++) {
            uint32_t phi[4], plo[4];
            #pragma unroll
            for (int t2 = 0; t2 < 2; t2++) {
                float x0 = sacc[2 * j + t2][0], x1 = sacc[2 * j + t2][1];
                float x2 = sacc[2 * j + t2][2], x3 = sacc[2 * j + t2][3];
                bf16 h0, l0, h1, l1, h2, l2, h3, l3;
                split1(x0, h0, l0); split1(x1, h1, l1);
                split1(x2, h2, l2); split1(x3, h3, l3);
                phi[t2 * 2 + 0] = packh(h0, h1);
                phi[t2 * 2 + 1] = packh(h2, h3);
                plo[t2 * 2 + 0] = packh(l0, l1);
                plo[t2 * 2 + 1] = packh(l2, l3);
            }
            #pragma unroll
            for (int nj = 0; nj < 8; nj++) {
                int rr = nj * 16 + brow;
                uint32_t cc = ((uint32_t)(j << 5) + bcolx) ^ ((uint32_t)(rr & 7) << 4);
                uint32_t vh4[4], vl4[4];
                ldsm4(vh4, sVh + (uint32_t)(rr * 128) + cc);
                ldsm4(vl4, sVl + (uint32_t)(rr * 128) + cc);
                #pragma unroll
                for (int t2 = 0; t2 < 2; t2++) {
                    float* o = oacc[nj * 2 + t2];
                    mma16816(o, phi, &vh4[t2 * 2]);
                    mma16816(o, phi, &vl4[t2 * 2]);
                    mma16816(o, plo, &vh4[t2 * 2]);
                }
            }
        }
        __syncthreads();                 // all warps done reading buffer
        if (kc + 1 < SEQ / 64) {
            loadkv(kc + 1);
            asm volatile("cp.async.wait_group 0;" ::: "memory");
            __syncthreads();
        }
    }

    // epilogue
    lsum0 += __shfl_xor_sync(0xffffffffu, lsum0, 1);
    lsum0 += __shfl_xor_sync(0xffffffffu, lsum0, 2);
    lsum1 += __shfl_xor_sync(0xffffffffu, lsum1, 1);
    lsum1 += __shfl_xor_sync(0xffffffffu, lsum1, 2);
    float inv0 = 1.0f / lsum0, inv1 = 1.0f / lsum1;
    bf16* Hh = g_Hhi + (size_t)b * SEQ * DMODEL + (size_t)h * HDIM;
    bf16* Hl = g_Hlo + (size_t)b * SEQ * DMODEL + (size_t)h * HDIM;
    const int r0r = q0 + m0 + (l >> 2);
    const int colb = (l & 3) * 2;
    #pragma unroll
    for (int nj = 0; nj < 16; nj++) {
        float x0 = oacc[nj][0] * inv0, x1 = oacc[nj][1] * inv0;
        float x2 = oacc[nj][2] * inv1, x3 = oacc[nj][3] * inv1;
        bf16 h0, l0, h1, l1, h2, l2, h3, l3;
        split1(x0, h0, l0); split1(x1, h1, l1);
        split1(x2, h2, l2); split1(x3, h3, l3);
        int col = nj * 8 + colb;
        *(uint32_t*)(Hh + (size_t)r0r * DMODEL + col) = packh(h0, h1);
        *(uint32_t*)(Hl + (size_t)r0r * DMODEL + col) = packh(l0, l1);
        *(uint32_t*)(Hh + (size_t)(r0r + 8) * DMODEL + col) = packh(h2, h3);
        *(uint32_t*)(Hl + (size_t)(r0r + 8) * DMODEL + col) = packh(l2, l3);
    }
}

// ------------------------- fused prep: split X + transpose-split weights -----
__device__ __forceinline__ void tr_split_body(const float* __restrict__ src,
                                              bf16* __restrict__ dhi,
                                              bf16* __restrict__ dlo,
                                              int R, int C, int bx, int by) {
    __shared__ float t[32][33];
    int r0 = by * 32, c0 = bx * 32;
    int tx = threadIdx.x & 31, ty = threadIdx.x >> 5;  // 32 x 8
    #pragma unroll
    for (int j = 0; j < 4; j++)
        t[ty + j * 8][tx] = src[(size_t)(r0 + ty + j * 8) * C + c0 + tx];
    __syncthreads();
    #pragma unroll
    for (int j = 0; j < 4; j++) {
        float v = t[tx][ty + j * 8];
        bf16 h, l;
        split1(v, h, l);
        size_t o = (size_t)(c0 + ty + j * 8) * R + r0 + tx;
        dhi[o] = h;
        dlo[o] = l;
    }
}

__global__ __launch_bounds__(256) void k_prep(const float* __restrict__ X,
                                              const float* __restrict__ Wq,
                                              const float* __restrict__ Wk,
                                              const float* __restrict__ Wv,
                                              const float* __restrict__ Wo) {
    int z = blockIdx.z;
    if (z == 0) { tr_split_body(Wq, g_WqThi, g_WqTlo, DMODEL, DMODEL, blockIdx.x, blockIdx.y); return; }
    if (z == 1) { tr_split_body(Wo, g_WoThi, g_WoTlo, DMODEL, DMODEL, blockIdx.x, blockIdx.y); return; }
    if (z == 2) { if (blockIdx.x < 4) tr_split_body(Wk, g_WkThi, g_WkTlo, DMODEL, HDIM, blockIdx.x, blockIdx.y); return; }
    if (z == 3) { if (blockIdx.x < 4) tr_split_body(Wv, g_WvThi, g_WvTlo, DMODEL, HDIM, blockIdx.x, blockIdx.y); return; }
    size_t bid = (size_t)(z - 4) * 4096 + blockIdx.y * 64 + blockIdx.x;
    size_t i = (bid * 256 + threadIdx.x) * 4;
    if (i >= (size_t)MROWS * DMODEL) return;
    float4 v = *(const float4*)(X + i);
    bf16 h0, l0, h1, l1, h2, l2, h3, l3;
    split1(v.x, h0, l0); split1(v.y, h1, l1);
    split1(v.z, h2, l2); split1(v.w, h3, l3);
    *(uint32_t*)(g_Xhi + i) = packh(h0, h1);
    *(uint32_t*)(g_Xhi + i + 2) = packh(h2, h3);
    *(uint32_t*)(g_Xlo + i) = packh(l0, l1);
    *(uint32_t*)(g_Xlo + i + 2) = packh(l2, l3);
}

// ------------------------- GEMM wrapper kernels -----------------------------
#define SMEM_GEMM 98304

__global__ __launch_bounds__(128, 2) void k_qproj() {
    gemm64(g_Xhi, g_Xlo, DMODEL, g_WqThi, g_WqTlo, DMODEL,
           DMODEL, blockIdx.y * 64, blockIdx.x * 128,
           1, SCALE, nullptr, g_Qhi, g_Qlo, DMODEL);
}

// z=0: K = X @ WkT (by = 64-token row block). z=1: V^T = WvT @ X^T
__global__ __launch_bounds__(128, 2) void k_kvT() {
    if (blockIdx.z == 0) {
        gemm64(g_Xhi, g_Xlo, DMODEL, g_WkThi, g_WkTlo, DMODEL,
               DMODEL, blockIdx.y * 64, 0,
               1, 1.0f, nullptr, g_Khi, g_Klo, HDIM);
    } else {
        int rowblk = blockIdx.y & 1;           // hd half (0..1)
        int tb = blockIdx.y >> 1;              // token block (0..31), 128 tokens
        int t0 = tb * 128;
        int b = t0 / SEQ, tl = t0 % SEQ;
        gemm64(g_WvThi, g_WvTlo, DMODEL,
               g_Xhi + (size_t)t0 * DMODEL, g_Xlo + (size_t)t0 * DMODEL, DMODEL,
               DMODEL, rowblk * 64, 0,
               1, 1.0f, nullptr,
               g_VThi + (size_t)b * HDIM * SEQ + tl,
               g_VTlo + (size_t)b * HDIM * SEQ + tl, SEQ);
    }
}

__global__ __launch_bounds__(128, 2) void k_outproj(float* __restrict__ out) {
    gemm64(g_Hhi, g_Hlo, DMODEL, g_WoThi, g_WoTlo, DMODEL,
           DMODEL, blockIdx.y * 64, blockIdx.x * 128,
           0, 1.0f, out, nullptr, nullptr, DMODEL);
}

// ------------------------- launch -------------------------------------------
extern "C" void kernel_launch(void* const* d_in, const int* in_sizes, int n_in,
                              void* d_out, int out_size) {
    const float* X  = (const float*)d_in[0];
    const float* Wq = (const float*)d_in[1];
    const float* Wk = (const float*)d_in[2];
    const float* Wv = (const float*)d_in[3];
    const float* Wo = (const float*)d_in[4];
    float* out = (float*)d_out;

    static int attr_done = 0;
    if (!attr_done) {
        attr_done = 1;
        cudaFuncSetAttribute(k_qproj,   cudaFuncAttributeMaxDynamicSharedMemorySize, SMEM_GEMM);
        cudaFuncSetAttribute(k_kvT,     cudaFuncAttributeMaxDynamicSharedMemorySize, SMEM_GEMM);
        cudaFuncSetAttribute(k_outproj, cudaFuncAttributeMaxDynamicSharedMemorySize, SMEM_GEMM);
        cudaFuncSetAttribute(k_flash,   cudaFuncAttributeMaxDynamicSharedMemorySize, SMEM_FLASH);
    }

    k_prep<<<dim3(64, 64, 6), 256>>>(X, Wq, Wk, Wv, Wo);
    k_qproj<<<dim3(DMODEL / 128, MROWS / 64), 128, SMEM_GEMM>>>();
    k_kvT<<<dim3(1, 64, 2), 128, SMEM_GEMM>>>();
    k_flash<<<dim3(SEQ / 64, BATCH * NHEAD), 128, SMEM_FLASH>>>();
    k_outproj<<<dim3(DMODEL / 128, MROWS / 64), 128, SMEM_GEMM>>>(out);
}